// round 14
// baseline (speedup 1.0000x reference)
#include <cuda_runtime.h>
#include <cuda_fp16.h>
#include <math.h>
#include <stdint.h>

// ===========================================================================
// VQ-VAE forward.  (R13 + deconv2 BN=256 N-merge: halves A-tile L2 traffic.)
// conv1+conv2: fp16 4-term split mma (one split GEMM pre-VQ argmin-safe;
// stacking a second (conv3) flips argmin -> conv3 stays exact fp32).
// conv3: exact fp32 SIMT split-K x8, TM=8. VQ exact fp32.
// Decoder deconv1/2: fp16 mma + ldmatrix (err ~1.3e-4, bit-stable).
// ===========================================================================

__device__ float g_h1[32 * 64 * 64 * 256];
__device__ float g_h2[32 * 32 * 32 * 512];
__device__ float g_zpart[8 * 8192 * 64];
__device__ float g_z [32 * 16 * 16 * 64];
__device__ float g_q [32 * 16 * 16 * 64];
__device__ float g_d1[32 * 32 * 32 * 512];
__device__ float g_d2[32 * 64 * 64 * 256];
__device__ float g_cnorm[512];
__device__ float g_partial[256];
__device__ int   g_used[512];
__device__ __align__(256) __half g_we1h[256 * 48],  g_we1l[256 * 48];
__device__ __align__(256) __half g_we2h[512 * 4096], g_we2l[512 * 4096];
__device__ __align__(256) __half g_wd1h[512 * 1024];
__device__ __align__(256) __half g_wd2h[256 * 8192];

__device__ __forceinline__ void mma_f16(float* c, const uint32_t* a, const uint32_t* b) {
    asm volatile(
        "mma.sync.aligned.m16n8k16.row.col.f32.f16.f16.f32 "
        "{%0,%1,%2,%3}, {%4,%5,%6,%7}, {%8,%9}, {%0,%1,%2,%3};"
        : "+f"(c[0]), "+f"(c[1]), "+f"(c[2]), "+f"(c[3])
        : "r"(a[0]), "r"(a[1]), "r"(a[2]), "r"(a[3]), "r"(b[0]), "r"(b[1]));
}
__device__ __forceinline__ void ldsm_x4(uint32_t* r, uint32_t addr) {
    asm volatile("ldmatrix.sync.aligned.m8n8.x4.shared.b16 {%0,%1,%2,%3}, [%4];"
        : "=r"(r[0]), "=r"(r[1]), "=r"(r[2]), "=r"(r[3]) : "r"(addr));
}
__device__ __forceinline__ void ldsm_x2(uint32_t* r, uint32_t addr) {
    asm volatile("ldmatrix.sync.aligned.m8n8.x2.shared.b16 {%0,%1}, [%2];"
        : "=r"(r[0]), "=r"(r[1]) : "r"(addr));
}
__device__ __forceinline__ uint32_t smem_u32(const void* p) {
    return (uint32_t)__cvta_generic_to_shared(p);
}

// ---------------------------------------------------------------------------
// cnorm + zero g_used (fused)
__global__ void cnorm_kernel(const float* __restrict__ cb) {
    int c = blockIdx.x * blockDim.x + threadIdx.x;
    if (c < 512) {
        float s = 0.f;
        #pragma unroll 8
        for (int j = 0; j < 64; j++) {
            float v = cb[c * 64 + j];
            s = fmaf(v, v, s);
        }
        g_cnorm[c] = s;
        g_used[c] = 0;
    }
}

__global__ __launch_bounds__(256) void wtrans_half(
    const float* __restrict__ w, __half* __restrict__ hi, int K, int N)
{
    __shared__ float t[32][33];
    int kb = blockIdx.x * 32, nb = blockIdx.y * 32;
    int x = threadIdx.x & 31, y0 = threadIdx.x >> 5;
    #pragma unroll
    for (int y = y0; y < 32; y += 8)
        t[y][x] = w[(size_t)(kb + y) * N + nb + x];
    __syncthreads();
    #pragma unroll
    for (int y = y0; y < 32; y += 8)
        hi[(size_t)(nb + y) * K + kb + x] = __float2half_rn(t[x][y]);
}

__global__ __launch_bounds__(256) void wtrans_half2(
    const float* __restrict__ w, __half* __restrict__ hi, __half* __restrict__ lo,
    int K, int N)
{
    __shared__ float t[32][33];
    int kb = blockIdx.x * 32, nb = blockIdx.y * 32;
    int x = threadIdx.x & 31, y0 = threadIdx.x >> 5;
    #pragma unroll
    for (int y = y0; y < 32; y += 8)
        t[y][x] = w[(size_t)(kb + y) * N + nb + x];
    __syncthreads();
    #pragma unroll
    for (int y = y0; y < 32; y += 8) {
        float v = t[x][y];
        __half h = __float2half_rn(v);
        hi[(size_t)(nb + y) * K + kb + x] = h;
        lo[(size_t)(nb + y) * K + kb + x] = __float2half_rn(v - __half2float(h));
    }
}

__global__ __launch_bounds__(256) void wtrans_c1(
    const float* __restrict__ w, __half* __restrict__ hi, __half* __restrict__ lo)
{
    int co = threadIdx.x;
    for (int ci = 0; ci < 3; ci++)
        for (int tap = 0; tap < 16; tap++) {
            float v = w[(tap * 3 + ci) * 256 + co];
            __half h = __float2half_rn(v);
            hi[co * 48 + ci * 16 + tap] = h;
            lo[co * 48 + ci * 16 + tap] = __float2half_rn(v - __half2float(h));
        }
}

// ---------------------------------------------------------------------------
// conv1 as 4-term fp16-split mma. M=131072, N=256, K=48 (k = ci*16 + tap).
// ---------------------------------------------------------------------------
__global__ __launch_bounds__(256) void mma_conv1(
    const float* __restrict__ x, const __half* __restrict__ whi,
    const __half* __restrict__ wlo, const float* __restrict__ bias,
    float* __restrict__ out)
{
    constexpr int BM = 128, LDAH = 24;
    constexpr int MI = 4, NI = 4;
    constexpr int NS = 3;
    constexpr int TP = BM * LDAH;
    constexpr int STAGE = 4 * TP;

    extern __shared__ __half smh[];
    const uint32_t sbase = smem_u32(smh);

    const int tid = threadIdx.x;
    const int wid = tid >> 5, lid = tid & 31;
    const int g = lid >> 2, t = lid & 3;
    const int wm0 = (wid >> 2) * 64;
    const int wn0 = (wid & 3) * 32;
    const int nblk = blockIdx.x * 128;
    const int mblk = blockIdx.y * BM;

    uint32_t offA[MI], offB[NI];
    #pragma unroll
    for (int mi = 0; mi < MI; mi++) {
        int rowA = wm0 + mi * 16 + ((lid >> 3) & 1) * 8 + (lid & 7);
        int koffA = (lid >> 4) * 8;
        offA[mi] = (uint32_t)(rowA * LDAH + koffA) * 2;
    }
    #pragma unroll
    for (int ni = 0; ni < NI; ni++) {
        int rowB = wn0 + ni * 8 + (lid & 7);
        int koffB = ((lid >> 3) & 1) * 8;
        offB[ni] = (uint32_t)(rowB * LDAH + koffB) * 2;
    }

    const int row = tid >> 1, h = tid & 1;
    const int m = mblk + row;
    const int ox = m % 64, oy = (m / 64) % 64, b = m / 4096;

    float av[8];
    uint4 bFh, bFl;

    auto loadRegs = [&](int ci) {
        #pragma unroll
        for (int kk = 0; kk < 2; kk++) {
            int kh = h * 2 + kk;
            int iy = 2 * oy - 1 + kh;
            #pragma unroll
            for (int kw = 0; kw < 4; kw++) {
                int ix = 2 * ox - 1 + kw;
                float v = 0.f;
                if (iy >= 0 && iy < 128 && ix >= 0 && ix < 128)
                    v = x[((b * 3 + ci) * 128 + iy) * 128 + ix];
                av[kk * 4 + kw] = v;
            }
        }
        bFh = *(const uint4*)&whi[(nblk + row) * 48 + ci * 16 + h * 8];
        bFl = *(const uint4*)&wlo[(nblk + row) * 48 + ci * 16 + h * 8];
    };
    auto storeSmem = [&](int buf) {
        __half* Ahi = smh + buf * STAGE;
        __half* Alo = Ahi + TP;
        __half* Bhi = Alo + TP;
        __half* Blo = Bhi + TP;
        __half hh[8], ll[8];
        #pragma unroll
        for (int j = 0; j < 8; j++) {
            __half hv = __float2half_rn(av[j]);
            hh[j] = hv;
            ll[j] = __float2half_rn(av[j] - __half2float(hv));
        }
        *(uint4*)&Ahi[row * LDAH + h * 8] = *(uint4*)hh;
        *(uint4*)&Alo[row * LDAH + h * 8] = *(uint4*)ll;
        *(uint4*)&Bhi[row * LDAH + h * 8] = bFh;
        *(uint4*)&Blo[row * LDAH + h * 8] = bFl;
    };

    float acc[MI][NI][4];
    #pragma unroll
    for (int mi = 0; mi < MI; mi++)
        #pragma unroll
        for (int ni = 0; ni < NI; ni++)
            #pragma unroll
            for (int c = 0; c < 4; c++) acc[mi][ni][c] = 0.f;

    loadRegs(0);
    storeSmem(0);
    __syncthreads();
    int buf = 0;
    #pragma unroll 1
    for (int s = 0; s < NS; s++) {
        if (s + 1 < NS) loadRegs(s + 1);
        uint32_t AhiB = sbase + (buf * STAGE) * 2;
        uint32_t AloB = AhiB + TP * 2;
        uint32_t BhiB = AloB + TP * 2;
        uint32_t BloB = BhiB + TP * 2;
        uint32_t ah[MI][4], al[MI][4], bh[NI][2], bl[NI][2];
        #pragma unroll
        for (int mi = 0; mi < MI; mi++) {
            ldsm_x4(ah[mi], AhiB + offA[mi]);
            ldsm_x4(al[mi], AloB + offA[mi]);
        }
        #pragma unroll
        for (int ni = 0; ni < NI; ni++) {
            ldsm_x2(bh[ni], BhiB + offB[ni]);
            ldsm_x2(bl[ni], BloB + offB[ni]);
        }
        #pragma unroll
        for (int mi = 0; mi < MI; mi++)
            #pragma unroll
            for (int ni = 0; ni < NI; ni++) {
                mma_f16(acc[mi][ni], ah[mi], bh[ni]);
                mma_f16(acc[mi][ni], ah[mi], bl[ni]);
                mma_f16(acc[mi][ni], al[mi], bh[ni]);
                mma_f16(acc[mi][ni], al[mi], bl[ni]);
            }
        if (s + 1 < NS) {
            storeSmem(buf ^ 1);
            __syncthreads();
            buf ^= 1;
        }
    }

    #pragma unroll
    for (int mi = 0; mi < MI; mi++) {
        #pragma unroll
        for (int half = 0; half < 2; half++) {
            int mo = mblk + wm0 + mi * 16 + g + half * 8;
            #pragma unroll
            for (int ni = 0; ni < NI; ni++) {
                int col = nblk + wn0 + ni * 8 + 2 * t;
                float2 bv = *(const float2*)&bias[col];
                float2 o;
                o.x = fmaxf(acc[mi][ni][half * 2 + 0] + bv.x, 0.f);
                o.y = fmaxf(acc[mi][ni][half * 2 + 1] + bv.y, 0.f);
                *(float2*)&out[(size_t)mo * 256 + col] = o;
            }
        }
    }
}

// ---------------------------------------------------------------------------
// conv2 as 4-term fp16-split mma, BK=16, ldmatrix (fastest measured form).
// ---------------------------------------------------------------------------
template<int Cin, int Cout, int IH, int IW, int OH, int OW>
__global__ __launch_bounds__(256) void mma_conv2(
    const float* __restrict__ in, const __half* __restrict__ whi,
    const __half* __restrict__ wlo, const float* __restrict__ bias,
    float* __restrict__ out)
{
    constexpr int BM = 128, BN = 128, BK = 16, LDAH = 24;
    constexpr int MI = 4, NI = 4;
    constexpr int NCI = Cin / BK;
    constexpr int NS = 16 * NCI;
    constexpr int Ktot = 16 * Cin;
    constexpr int TP = BM * LDAH;
    constexpr int STAGE = 4 * TP;

    extern __shared__ __half smh[];
    const uint32_t sbase = smem_u32(smh);

    const int tid = threadIdx.x;
    const int wid = tid >> 5, lid = tid & 31;
    const int g = lid >> 2, t = lid & 3;
    const int wm0 = (wid >> 2) * 64;
    const int wn0 = (wid & 3) * 32;
    const int nblk = blockIdx.x * BN;
    const int mblk = blockIdx.y * BM;

    uint32_t offA[MI], offB[NI];
    #pragma unroll
    for (int mi = 0; mi < MI; mi++) {
        int rowA = wm0 + mi * 16 + ((lid >> 3) & 1) * 8 + (lid & 7);
        int koffA = (lid >> 4) * 8;
        offA[mi] = (uint32_t)(rowA * LDAH + koffA) * 2;
    }
    #pragma unroll
    for (int ni = 0; ni < NI; ni++) {
        int rowB = wn0 + ni * 8 + (lid & 7);
        int koffB = ((lid >> 3) & 1) * 8;
        offB[ni] = (uint32_t)(rowB * LDAH + koffB) * 2;
    }

    float4 aF0, aF1;
    uint4 bFh, bFl;

    auto loadRegs = [&](int s) {
        const int tap = s / NCI;
        const int ci0 = (s - tap * NCI) * BK;
        const int kh = tap >> 2, kw = tap & 3;
        const int row = tid >> 1, h8 = tid & 1;
        int m = mblk + row;
        int ox = m % OW; int tmp = m / OW; int oy = tmp % OH; int b = tmp / OH;
        int iy = 2 * oy - 1 + kh, ix = 2 * ox - 1 + kw;
        bool ok = (iy >= 0 && iy < IH && ix >= 0 && ix < IW);
        const float* gp = in + (size_t)((b * IH + iy) * IW + ix) * Cin + ci0 + h8 * 8;
        aF0 = ok ? *(const float4*)gp       : make_float4(0.f, 0.f, 0.f, 0.f);
        aF1 = ok ? *(const float4*)(gp + 4) : make_float4(0.f, 0.f, 0.f, 0.f);
        const int kbase = (kh * 4 + kw) * Cin + ci0 + h8 * 8;
        bFh = *(const uint4*)&whi[(size_t)(nblk + row) * Ktot + kbase];
        bFl = *(const uint4*)&wlo[(size_t)(nblk + row) * Ktot + kbase];
    };
    auto storeSmem = [&](int buf) {
        const int row = tid >> 1, h8 = tid & 1;
        __half* Ahi = smh + buf * STAGE;
        __half* Alo = Ahi + TP;
        __half* Bhi = Alo + TP;
        __half* Blo = Bhi + TP;
        float vs[8] = {aF0.x, aF0.y, aF0.z, aF0.w, aF1.x, aF1.y, aF1.z, aF1.w};
        __half hh[8], ll[8];
        #pragma unroll
        for (int j = 0; j < 8; j++) {
            __half hv = __float2half_rn(vs[j]);
            hh[j] = hv;
            ll[j] = __float2half_rn(vs[j] - __half2float(hv));
        }
        *(uint4*)&Ahi[row * LDAH + h8 * 8] = *(uint4*)hh;
        *(uint4*)&Alo[row * LDAH + h8 * 8] = *(uint4*)ll;
        *(uint4*)&Bhi[row * LDAH + h8 * 8] = bFh;
        *(uint4*)&Blo[row * LDAH + h8 * 8] = bFl;
    };

    float acc[MI][NI][4];
    #pragma unroll
    for (int mi = 0; mi < MI; mi++)
        #pragma unroll
        for (int ni = 0; ni < NI; ni++)
            #pragma unroll
            for (int c = 0; c < 4; c++) acc[mi][ni][c] = 0.f;

    loadRegs(0);
    storeSmem(0);
    __syncthreads();
    int buf = 0;
    #pragma unroll 1
    for (int s = 0; s < NS; s++) {
        if (s + 1 < NS) loadRegs(s + 1);
        uint32_t AhiB = sbase + (buf * STAGE) * 2;
        uint32_t AloB = AhiB + TP * 2;
        uint32_t BhiB = AloB + TP * 2;
        uint32_t BloB = BhiB + TP * 2;
        uint32_t ah[MI][4], al[MI][4], bh[NI][2], bl[NI][2];
        #pragma unroll
        for (int mi = 0; mi < MI; mi++) {
            ldsm_x4(ah[mi], AhiB + offA[mi]);
            ldsm_x4(al[mi], AloB + offA[mi]);
        }
        #pragma unroll
        for (int ni = 0; ni < NI; ni++) {
            ldsm_x2(bh[ni], BhiB + offB[ni]);
            ldsm_x2(bl[ni], BloB + offB[ni]);
        }
        #pragma unroll
        for (int mi = 0; mi < MI; mi++)
            #pragma unroll
            for (int ni = 0; ni < NI; ni++) {
                mma_f16(acc[mi][ni], ah[mi], bh[ni]);
                mma_f16(acc[mi][ni], ah[mi], bl[ni]);
                mma_f16(acc[mi][ni], al[mi], bh[ni]);
                mma_f16(acc[mi][ni], al[mi], bl[ni]);
            }
        if (s + 1 < NS) {
            storeSmem(buf ^ 1);
            __syncthreads();
            buf ^= 1;
        }
    }

    #pragma unroll
    for (int mi = 0; mi < MI; mi++) {
        #pragma unroll
        for (int half = 0; half < 2; half++) {
            int m = mblk + wm0 + mi * 16 + g + half * 8;
            #pragma unroll
            for (int ni = 0; ni < NI; ni++) {
                int col = nblk + wn0 + ni * 8 + 2 * t;
                float2 bv = *(const float2*)&bias[col];
                float2 o;
                o.x = fmaxf(acc[mi][ni][half * 2 + 0] + bv.x, 0.f);
                o.y = fmaxf(acc[mi][ni][half * 2 + 1] + bv.y, 0.f);
                *(float2*)&out[(size_t)m * Cout + col] = o;
            }
        }
    }
}

// ---------------------------------------------------------------------------
// conv3: exact fp32 SIMT implicit GEMM, split-K x8 (argmin-critical; exact).
// ---------------------------------------------------------------------------
template<int BM, int BN, int BK, int TM, int TN,
         int Cin, int Cout, int IH, int IW, int OH, int OW, int KSPLIT>
__global__ __launch_bounds__(256) void conv_s2_gemm(
    const float* __restrict__ in, const float* __restrict__ w,
    const float* __restrict__ bias, float* __restrict__ out)
{
    static_assert((BM / TM) * (BN / TN) == 256, "thread count");
    constexpr int NCI   = Cin / BK;
    constexpr int NS    = 16 * NCI;
    constexpr int NSC   = NS / KSPLIT;
    constexpr int MTOT  = 32 * OH * OW;
    constexpr int ALOOP = (BM * BK / 4) / 256;
    constexpr int BLOOP = (BK * BN / 4) / 256;
    static_assert(ALOOP >= 1 && BLOOP >= 1, "load split");
    static_assert(NSC >= 2, "pipeline");

    __shared__ __align__(16) float As[2][BK][BM + 4];
    __shared__ __align__(16) float Bs[2][BK][BN + 4];

    const int tid  = threadIdx.x;
    const int mblk = blockIdx.y * BM;
    const int kc   = (KSPLIT > 1) ? (int)blockIdx.x : 0;
    const int nblk = (KSPLIT > 1) ? 0 : blockIdx.x * BN;

    float4 areg[ALOOP], breg[BLOOP];

    auto loadRegs = [&](int s) {
        int t16 = s / NCI;
        int ci0 = (s % NCI) * BK;
        int kh = t16 >> 2, kw = t16 & 3;
        #pragma unroll
        for (int i = 0; i < ALOOP; i++) {
            int idx = tid + i * 256;
            int row = idx / (BK / 4);
            int c4  = idx % (BK / 4);
            int m   = mblk + row;
            int ox  = m % OW;
            int tmp = m / OW;
            int oy  = tmp % OH;
            int b   = tmp / OH;
            int iy  = 2 * oy - 1 + kh;
            int ix  = 2 * ox - 1 + kw;
            if (iy >= 0 && iy < IH && ix >= 0 && ix < IW)
                areg[i] = *(const float4*)&in[((b * IH + iy) * IW + ix) * Cin + ci0 + c4 * 4];
            else
                areg[i] = make_float4(0.f, 0.f, 0.f, 0.f);
        }
        #pragma unroll
        for (int i = 0; i < BLOOP; i++) {
            int idx  = tid + i * 256;
            int krow = idx / (BN / 4);
            int c4   = idx % (BN / 4);
            breg[i] = *(const float4*)&w[(t16 * Cin + ci0 + krow) * Cout + nblk + c4 * 4];
        }
    };
    auto storeSmem = [&](int buf) {
        #pragma unroll
        for (int i = 0; i < ALOOP; i++) {
            int idx = tid + i * 256;
            int row = idx / (BK / 4);
            int c4  = idx % (BK / 4);
            As[buf][c4 * 4 + 0][row] = areg[i].x;
            As[buf][c4 * 4 + 1][row] = areg[i].y;
            As[buf][c4 * 4 + 2][row] = areg[i].z;
            As[buf][c4 * 4 + 3][row] = areg[i].w;
        }
        #pragma unroll
        for (int i = 0; i < BLOOP; i++) {
            int idx  = tid + i * 256;
            int krow = idx / (BN / 4);
            int c4   = idx % (BN / 4);
            *(float4*)&Bs[buf][krow][c4 * 4] = breg[i];
        }
    };

    const int ty = tid / (BN / TN);
    const int tx = tid % (BN / TN);
    float acc[TM][TN];
    #pragma unroll
    for (int i = 0; i < TM; i++)
        #pragma unroll
        for (int j = 0; j < TN; j++) acc[i][j] = 0.f;

    const int s0 = kc * NSC;
    loadRegs(s0);
    storeSmem(0);
    __syncthreads();
    int buf = 0;
    for (int s = s0; s < s0 + NSC; s++) {
        if (s + 1 < s0 + NSC) loadRegs(s + 1);
        #pragma unroll
        for (int kk = 0; kk < BK; kk++) {
            float a[TM], bb[TN];
            #pragma unroll
            for (int i = 0; i < TM; i += 4)
                *(float4*)&a[i] = *(const float4*)&As[buf][kk][ty * TM + i];
            #pragma unroll
            for (int j = 0; j < TN; j += 4)
                *(float4*)&bb[j] = *(const float4*)&Bs[buf][kk][tx * TN + j];
            #pragma unroll
            for (int i = 0; i < TM; i++)
                #pragma unroll
                for (int j = 0; j < TN; j++)
                    acc[i][j] = fmaf(a[i], bb[j], acc[i][j]);
        }
        if (s + 1 < s0 + NSC) {
            storeSmem(buf ^ 1);
            __syncthreads();
            buf ^= 1;
        }
    }
    #pragma unroll
    for (int i = 0; i < TM; i++) {
        int m = mblk + ty * TM + i;
        #pragma unroll
        for (int j = 0; j < TN; j++) {
            int n = nblk + tx * TN + j;
            if (KSPLIT > 1) {
                out[(size_t)kc * MTOT * Cout + (size_t)m * Cout + n] = acc[i][j];
            } else {
                float v = acc[i][j] + bias[n];
                out[(size_t)m * Cout + n] = fmaxf(v, 0.f);
            }
        }
    }
}

__global__ __launch_bounds__(256) void reduce_z_kernel(const float* __restrict__ bias) {
    int i = blockIdx.x * 256 + threadIdx.x;
    float s = 0.f;
    #pragma unroll
    for (int kc = 0; kc < 8; kc++)
        s += g_zpart[kc * 8192 * 64 + i];
    g_z[i] = fmaxf(s + bias[i & 63], 0.f);
}

// ---------------------------------------------------------------------------
// Decoder transposed conv: fp16 mma with ldmatrix frag loads.
// BN=128: B row per thread-pair (8 halves). BN=256: B row per thread (16).
// ---------------------------------------------------------------------------
template<int BM, int BN, int WARPS_M, int WARPS_N, int Cin, int Cout,
         int ISP, int OSP>
__global__ __launch_bounds__(256) void mma_deconv(
    const float* __restrict__ in, const __half* __restrict__ wth,
    const float* __restrict__ bias, float* __restrict__ out)
{
    constexpr int BK = 16, LDAH = 24;
    constexpr int WM = BM / WARPS_M, WN = BN / WARPS_N;
    constexpr int MI = WM / 16, NI = WN / 8;
    constexpr int NCI = Cin / BK;
    constexpr int NS = 4 * NCI;
    constexpr int Ktot = 16 * Cin;
    constexpr int ALOOP = (BM * 4) / 256;
    constexpr int APITCH = BM * LDAH;
    constexpr int BPITCH = BN * LDAH;
    static_assert(WARPS_M * WARPS_N == 8, "8 warps");
    static_assert(ALOOP >= 1, "load split");
    static_assert(BN == 128 || BN == 256, "B load mapping");

    extern __shared__ __half smh[];
    __half* Abase = smh;
    __half* Bbase = smh + 2 * APITCH;
    const uint32_t sbase = smem_u32(smh);

    const int tid = threadIdx.x;
    const int wid = tid >> 5, lid = tid & 31;
    const int g = lid >> 2, t = lid & 3;
    const int wm0 = (wid / WARPS_N) * WM;
    const int wn0 = (wid % WARPS_N) * WN;
    const int nblk = blockIdx.x * BN;
    const int mblk = blockIdx.y * BM;
    const int par  = blockIdx.z;
    const int py = par >> 1, px = par & 1;

    uint32_t offA[MI], offB[NI];
    #pragma unroll
    for (int mi = 0; mi < MI; mi++) {
        int rowA = wm0 + mi * 16 + ((lid >> 3) & 1) * 8 + (lid & 7);
        int koffA = (lid >> 4) * 8;
        offA[mi] = (uint32_t)(rowA * LDAH + koffA) * 2;
    }
    #pragma unroll
    for (int ni = 0; ni < NI; ni++) {
        int rowB = wn0 + ni * 8 + (lid & 7);
        int koffB = ((lid >> 3) & 1) * 8;
        offB[ni] = (uint32_t)(rowB * LDAH + koffB) * 2;
    }

    float4 aF[ALOOP];
    uint4  bF0, bF1;

    auto loadRegs = [&](int s) {
        const int tap = s / NCI;
        const int ci0 = (s - tap * NCI) * BK;
        int tyk = tap >> 1, txk = tap & 1;
        int kh = (py ? 2 : 3) - 2 * tyk;
        int kw = (px ? 2 : 3) - 2 * txk;
        #pragma unroll
        for (int i = 0; i < ALOOP; i++) {
            int slot = tid + i * 256;
            int row = slot >> 2, c4 = slot & 3;
            int m = mblk + row;
            int mx = m % ISP; int t2 = m / ISP; int my = t2 % ISP; int b = t2 / ISP;
            int iy = my + tyk - 1 + py;
            int ix = mx + txk - 1 + px;
            bool ok = (iy >= 0 && iy < ISP && ix >= 0 && ix < ISP);
            aF[i] = ok ? *(const float4*)&in[(size_t)((b * ISP + iy) * ISP + ix) * Cin + ci0 + c4 * 4]
                       : make_float4(0.f, 0.f, 0.f, 0.f);
        }
        const int kbase = (kh * 4 + kw) * Cin + ci0;
        if (BN == 128) {
            int row = tid >> 1, h8 = tid & 1;
            bF0 = *(const uint4*)&wth[(size_t)(nblk + row) * Ktot + kbase + h8 * 8];
        } else {
            int row = tid;
            const __half* bp = &wth[(size_t)(nblk + row) * Ktot + kbase];
            bF0 = *(const uint4*)bp;
            bF1 = *(const uint4*)(bp + 8);
        }
    };
    auto storeSmem = [&](int buf) {
        #pragma unroll
        for (int i = 0; i < ALOOP; i++) {
            int slot = tid + i * 256;
            int row = slot >> 2, c4 = slot & 3;
            float4 v = aF[i];
            __half2 p0 = __floats2half2_rn(v.x, v.y);
            __half2 p1 = __floats2half2_rn(v.z, v.w);
            uint2 st;
            st.x = *(uint32_t*)&p0;
            st.y = *(uint32_t*)&p1;
            *(uint2*)&Abase[buf * APITCH + row * LDAH + c4 * 4] = st;
        }
        if (BN == 128) {
            int row = tid >> 1, h8 = tid & 1;
            *(uint4*)&Bbase[buf * BPITCH + row * LDAH + h8 * 8] = bF0;
        } else {
            int row = tid;
            *(uint4*)&Bbase[buf * BPITCH + row * LDAH] = bF0;
            *(uint4*)&Bbase[buf * BPITCH + row * LDAH + 8] = bF1;
        }
    };

    float acc[MI][NI][4];
    #pragma unroll
    for (int mi = 0; mi < MI; mi++)
        #pragma unroll
        for (int ni = 0; ni < NI; ni++)
            #pragma unroll
            for (int c = 0; c < 4; c++) acc[mi][ni][c] = 0.f;

    loadRegs(0);
    storeSmem(0);
    __syncthreads();
    int buf = 0;
    #pragma unroll 1
    for (int s = 0; s < NS; s++) {
        if (s + 1 < NS) loadRegs(s + 1);
        uint32_t AB = sbase + (buf * APITCH) * 2;
        uint32_t BB = sbase + (2 * APITCH + buf * BPITCH) * 2;
        uint32_t au[MI][4], bu[NI][2];
        #pragma unroll
        for (int mi = 0; mi < MI; mi++)
            ldsm_x4(au[mi], AB + offA[mi]);
        #pragma unroll
        for (int ni = 0; ni < NI; ni++)
            ldsm_x2(bu[ni], BB + offB[ni]);
        #pragma unroll
        for (int mi = 0; mi < MI; mi++)
            #pragma unroll
            for (int ni = 0; ni < NI; ni++)
                mma_f16(acc[mi][ni], au[mi], bu[ni]);
        if (s + 1 < NS) {
            storeSmem(buf ^ 1);
            __syncthreads();
            buf ^= 1;
        }
    }

    #pragma unroll
    for (int mi = 0; mi < MI; mi++) {
        #pragma unroll
        for (int half = 0; half < 2; half++) {
            int m = mblk + wm0 + mi * 16 + g + half * 8;
            int mx = m % ISP; int t2 = m / ISP; int my = t2 % ISP; int b = t2 / ISP;
            size_t obase = ((size_t)(b * OSP + 2 * my + py) * OSP + 2 * mx + px) * Cout;
            #pragma unroll
            for (int ni = 0; ni < NI; ni++) {
                int col = nblk + wn0 + ni * 8 + 2 * t;
                float2 bv = *(const float2*)&bias[col];
                float2 o;
                o.x = fmaxf(acc[mi][ni][half * 2 + 0] + bv.x, 0.f);
                o.y = fmaxf(acc[mi][ni][half * 2 + 1] + bv.y, 0.f);
                *(float2*)&out[obase + col] = o;
            }
        }
    }
}

// ---------------------------------------------------------------------------
// VQ: 8 lane-groups per pixel over 64 codes each; shfl argmin reduce with
// first-index tie rule. Exact fp32.
// ---------------------------------------------------------------------------
__global__ __launch_bounds__(256) void vq_kernel(const float* __restrict__ cb) {
    const int lid = threadIdx.x & 31, wrp = threadIdx.x >> 5;
    const int pixw = lid & 3, grp = lid >> 2;
    const int p = blockIdx.x * 32 + wrp * 4 + pixw;

    float z[64];
    const float4* zp = (const float4*)&g_z[p * 64];
    #pragma unroll
    for (int j4 = 0; j4 < 16; j4++) {
        float4 v = zp[j4];
        z[j4 * 4 + 0] = v.x; z[j4 * 4 + 1] = v.y;
        z[j4 * 4 + 2] = v.z; z[j4 * 4 + 3] = v.w;
    }
    float best = 3.4e38f;
    int bi = 0;
    for (int c = grp * 64; c < grp * 64 + 64; c++) {
        const float4* cp = (const float4*)&cb[c * 64];
        float dot = 0.f;
        #pragma unroll
        for (int j4 = 0; j4 < 16; j4++) {
            float4 v = __ldg(&cp[j4]);
            dot = fmaf(z[j4 * 4 + 0], v.x, dot);
            dot = fmaf(z[j4 * 4 + 1], v.y, dot);
            dot = fmaf(z[j4 * 4 + 2], v.z, dot);
            dot = fmaf(z[j4 * 4 + 3], v.w, dot);
        }
        float d = g_cnorm[c] - 2.f * dot;
        if (d < best) { best = d; bi = c; }
    }
    #pragma unroll
    for (int off = 4; off <= 16; off <<= 1) {
        float ob = __shfl_xor_sync(0xFFFFFFFFu, best, off);
        int  obi = __shfl_xor_sync(0xFFFFFFFFu, bi,   off);
        if (ob < best || (ob == best && obi < bi)) { best = ob; bi = obi; }
    }

    float ls = 0.f;
    if (grp == 0) {
        float4* qp = (float4*)&g_q[p * 64];
        const float4* cbest = (const float4*)&cb[bi * 64];
        #pragma unroll
        for (int j4 = 0; j4 < 16; j4++) {
            float4 v = cbest[j4];
            qp[j4] = v;
            float d0 = z[j4 * 4 + 0] - v.x;
            float d1 = z[j4 * 4 + 1] - v.y;
            float d2 = z[j4 * 4 + 2] - v.z;
            float d3 = z[j4 * 4 + 3] - v.w;
            ls = fmaf(d0, d0, ls); ls = fmaf(d1, d1, ls);
            ls = fmaf(d2, d2, ls); ls = fmaf(d3, d3, ls);
        }
        g_used[bi] = 1;
    }

    __shared__ float red[256];
    red[threadIdx.x] = ls;
    __syncthreads();
    for (int s2 = 128; s2 > 0; s2 >>= 1) {
        if (threadIdx.x < s2) red[threadIdx.x] += red[threadIdx.x + s2];
        __syncthreads();
    }
    if (threadIdx.x == 0) g_partial[blockIdx.x] = red[0];
}

// ---------------------------------------------------------------------------
// deconv3: 256->3, sigmoid, NHWC in -> NCHW out (exact). 2 rows per block.
// Weights in smem transposed to [tap][c][ci] for float4 loads.
// ---------------------------------------------------------------------------
__global__ __launch_bounds__(256) void deconv3_kernel(
    const float* __restrict__ in, const float* __restrict__ w,
    const float* __restrict__ bias, float* __restrict__ out)
{
    __shared__ float ws[16 * 3 * 256];   // [tap][c][ci]
    for (int i = threadIdx.x; i < 16 * 3 * 256; i += 256) {
        int tap = i / 768;
        int rem = i - tap * 768;
        int c = rem >> 8;
        int ci = rem & 255;
        ws[i] = w[(tap * 256 + ci) * 3 + c];
    }
    __syncthreads();

    int b  = blockIdx.x >> 6;
    int oy = ((blockIdx.x & 63) << 1) | (threadIdx.x >> 7);
    int ox = threadIdx.x & 127;
    int py = oy & 1, px = ox & 1;
    int my = oy >> 1, mx = ox >> 1;

    float acc0 = bias[0], acc1 = bias[1], acc2 = bias[2];
    #pragma unroll
    for (int t = 0; t < 4; t++) {
        int tyk = t >> 1, txk = t & 1;
        int iy = my + tyk - 1 + py;
        int ix = mx + txk - 1 + px;
        if (iy < 0 || iy >= 64 || ix < 0 || ix >= 64) continue;
        int kh = (py ? 2 : 3) - 2 * tyk;
        int kw = (px ? 2 : 3) - 2 * txk;
        const float* ip  = &in[((b * 64 + iy) * 64 + ix) * 256];
        const float* wp0 = &ws[((kh * 4 + kw) * 3 + 0) * 256];
        const float* wp1 = &ws[((kh * 4 + kw) * 3 + 1) * 256];
        const float* wp2 = &ws[((kh * 4 + kw) * 3 + 2) * 256];
        #pragma unroll 8
        for (int ci = 0; ci < 256; ci += 4) {
            float4 v  = *(const float4*)&ip[ci];
            float4 w0 = *(const float4*)&wp0[ci];
            float4 w1 = *(const float4*)&wp1[ci];
            float4 w2 = *(const float4*)&wp2[ci];
            acc0 = fmaf(v.x, w0.x, acc0);
            acc1 = fmaf(v.x, w1.x, acc1);
            acc2 = fmaf(v.x, w2.x, acc2);
            acc0 = fmaf(v.y, w0.y, acc0);
            acc1 = fmaf(v.y, w1.y, acc1);
            acc2 = fmaf(v.y, w2.y, acc2);
            acc0 = fmaf(v.z, w0.z, acc0);
            acc1 = fmaf(v.z, w1.z, acc1);
            acc2 = fmaf(v.z, w2.z, acc2);
            acc0 = fmaf(v.w, w0.w, acc0);
            acc1 = fmaf(v.w, w1.w, acc1);
            acc2 = fmaf(v.w, w2.w, acc2);
        }
    }
    out[((b * 3 + 0) * 128 + oy) * 128 + ox] = 1.f / (1.f + expf(-acc0));
    out[((b * 3 + 1) * 128 + oy) * 128 + ox] = 1.f / (1.f + expf(-acc1));
    out[((b * 3 + 2) * 128 + oy) * 128 + ox] = 1.f / (1.f + expf(-acc2));
}

__global__ void finalize_kernel(float* __restrict__ out, int out_size) {
    __shared__ int total;
    int t = threadIdx.x;
    if (t == 0) total = 0;
    __syncthreads();
    if (t < 512 && g_used[t]) atomicAdd(&total, 1);
    __syncthreads();
    if (t == 0) {
        float sum = 0.f;
        for (int i = 0; i < 256; i++) sum += g_partial[i];
        float mean = sum / (float)(8192 * 64);
        out[out_size - 3] = mean;
        out[out_size - 2] = mean;
        out[out_size - 1] = (float)total;
    }
}

// ---------------------------------------------------------------------------
extern "C" void kernel_launch(void* const* d_in, const int* in_sizes, int n_in,
                              void* d_out, int out_size)
{
    const float* x   = (const float*)d_in[0];
    const float* ew1 = (const float*)d_in[1];
    const float* eb1 = (const float*)d_in[2];
    const float* ew2 = (const float*)d_in[3];
    const float* eb2 = (const float*)d_in[4];
    const float* ew3 = (const float*)d_in[5];
    const float* eb3 = (const float*)d_in[6];
    const float* cb  = (const float*)d_in[7];
    const float* dw1 = (const float*)d_in[8];
    const float* db1 = (const float*)d_in[9];
    const float* dw2 = (const float*)d_in[10];
    const float* db2 = (const float*)d_in[11];
    const float* dw3 = (const float*)d_in[12];
    const float* db3 = (const float*)d_in[13];
    float* out = (float*)d_out;

    float *h1, *h2, *zpart, *q, *d1, *d2;
    __half *we1h, *we1l, *we2h, *we2l, *wd1h, *wd2h;
    cudaGetSymbolAddress((void**)&h1, g_h1);
    cudaGetSymbolAddress((void**)&h2, g_h2);
    cudaGetSymbolAddress((void**)&zpart, g_zpart);
    cudaGetSymbolAddress((void**)&q,  g_q);
    cudaGetSymbolAddress((void**)&d1, g_d1);
    cudaGetSymbolAddress((void**)&d2, g_d2);
    cudaGetSymbolAddress((void**)&we1h, g_we1h);
    cudaGetSymbolAddress((void**)&we1l, g_we1l);
    cudaGetSymbolAddress((void**)&we2h, g_we2h);
    cudaGetSymbolAddress((void**)&we2l, g_we2l);
    cudaGetSymbolAddress((void**)&wd1h, g_wd1h);
    cudaGetSymbolAddress((void**)&wd2h, g_wd2h);

    const int SM_DEC1 = 2 * (128 * 24 + 128 * 24) * 2;  // 24576 B
    const int SM_DEC2 = 2 * (64 * 24 + 256 * 24) * 2;   // 30720 B
    const int SM_MMA  = 2 * 4 * 128 * 24 * 2;           // 49152 B
    cudaFuncSetAttribute(mma_conv1,
                         cudaFuncAttributeMaxDynamicSharedMemorySize, SM_MMA);
    cudaFuncSetAttribute(mma_conv2<256, 512, 64, 64, 32, 32>,
                         cudaFuncAttributeMaxDynamicSharedMemorySize, SM_MMA);

    cnorm_kernel<<<2, 256>>>(cb);

    // weight prep
    wtrans_c1<<<1, 256>>>(ew1, we1h, we1l);
    wtrans_half2<<<dim3(4096 / 32, 512 / 32), 256>>>(ew2, we2h, we2l, 4096, 512);
    wtrans_half<<<dim3(1024 / 32, 512 / 32), 256>>>(dw1, wd1h, 1024, 512);
    wtrans_half<<<dim3(8192 / 32, 256 / 32), 256>>>(dw2, wd2h, 8192, 256);

    // encoder
    mma_conv1<<<dim3(2, 1024), 256, SM_MMA>>>(x, we1h, we1l, eb1, h1);
    mma_conv2<256, 512, 64, 64, 32, 32>
        <<<dim3(4, 256), 256, SM_MMA>>>(h1, we2h, we2l, eb2, h2);
    conv_s2_gemm<128, 64, 16, 8, 4, 512, 64, 32, 32, 16, 16, 8>
        <<<dim3(8, 64), 256>>>(h2, ew3, eb3, zpart);
    reduce_z_kernel<<<2048, 256>>>(eb3);

    // vector quantize (exact)
    vq_kernel<<<256, 256>>>(cb);

    // decoder (fp16 tensor, ldmatrix)
    mma_deconv<128, 128, 2, 4, 64, 512, 16, 32>
        <<<dim3(4, 64, 4), 256, SM_DEC1>>>(q, wd1h, db1, d1);
    mma_deconv<64, 256, 2, 4, 512, 256, 32, 64>
        <<<dim3(1, 512, 4), 256, SM_DEC2>>>(d1, wd2h, db2, d2);
    deconv3_kernel<<<32 * 64, 256>>>(d2, dw3, db3, out);

    finalize_kernel<<<1, 512>>>(out, out_size);
}

// round 15
// speedup vs baseline: 1.1140x; 1.1140x over previous
#include <cuda_runtime.h>
#include <cuda_fp16.h>
#include <math.h>
#include <stdint.h>

// ===========================================================================
// VQ-VAE forward.  (R13 + conv1 emits h1 pre-split hi/lo fp16 for conv2.)
// conv1+conv2: fp16 4-term split mma (one split GEMM pre-VQ argmin-safe;
// stacking a second (conv3) flips argmin -> conv3 stays exact fp32).
// conv3: exact fp32 SIMT split-K x8, TM=8. VQ exact fp32.
// Decoder deconv1/2: fp16 mma + ldmatrix, 128x128 tiles (err ~1.3e-4).
// ===========================================================================

__device__ __align__(256) __half g_h1h[32 * 64 * 64 * 256];
__device__ __align__(256) __half g_h1l[32 * 64 * 64 * 256];
__device__ float g_h2[32 * 32 * 32 * 512];
__device__ float g_zpart[8 * 8192 * 64];
__device__ float g_z [32 * 16 * 16 * 64];
__device__ float g_q [32 * 16 * 16 * 64];
__device__ float g_d1[32 * 32 * 32 * 512];
__device__ float g_d2[32 * 64 * 64 * 256];
__device__ float g_cnorm[512];
__device__ float g_partial[256];
__device__ int   g_used[512];
__device__ __align__(256) __half g_we1h[256 * 48],  g_we1l[256 * 48];
__device__ __align__(256) __half g_we2h[512 * 4096], g_we2l[512 * 4096];
__device__ __align__(256) __half g_wd1h[512 * 1024];
__device__ __align__(256) __half g_wd2h[256 * 8192];

__device__ __forceinline__ void mma_f16(float* c, const uint32_t* a, const uint32_t* b) {
    asm volatile(
        "mma.sync.aligned.m16n8k16.row.col.f32.f16.f16.f32 "
        "{%0,%1,%2,%3}, {%4,%5,%6,%7}, {%8,%9}, {%0,%1,%2,%3};"
        : "+f"(c[0]), "+f"(c[1]), "+f"(c[2]), "+f"(c[3])
        : "r"(a[0]), "r"(a[1]), "r"(a[2]), "r"(a[3]), "r"(b[0]), "r"(b[1]));
}
__device__ __forceinline__ void ldsm_x4(uint32_t* r, uint32_t addr) {
    asm volatile("ldmatrix.sync.aligned.m8n8.x4.shared.b16 {%0,%1,%2,%3}, [%4];"
        : "=r"(r[0]), "=r"(r[1]), "=r"(r[2]), "=r"(r[3]) : "r"(addr));
}
__device__ __forceinline__ void ldsm_x2(uint32_t* r, uint32_t addr) {
    asm volatile("ldmatrix.sync.aligned.m8n8.x2.shared.b16 {%0,%1}, [%2];"
        : "=r"(r[0]), "=r"(r[1]) : "r"(addr));
}
__device__ __forceinline__ uint32_t smem_u32(const void* p) {
    return (uint32_t)__cvta_generic_to_shared(p);
}

// ---------------------------------------------------------------------------
// cnorm + zero g_used (fused)
__global__ void cnorm_kernel(const float* __restrict__ cb) {
    int c = blockIdx.x * blockDim.x + threadIdx.x;
    if (c < 512) {
        float s = 0.f;
        #pragma unroll 8
        for (int j = 0; j < 64; j++) {
            float v = cb[c * 64 + j];
            s = fmaf(v, v, s);
        }
        g_cnorm[c] = s;
        g_used[c] = 0;
    }
}

__global__ __launch_bounds__(256) void wtrans_half(
    const float* __restrict__ w, __half* __restrict__ hi, int K, int N)
{
    __shared__ float t[32][33];
    int kb = blockIdx.x * 32, nb = blockIdx.y * 32;
    int x = threadIdx.x & 31, y0 = threadIdx.x >> 5;
    #pragma unroll
    for (int y = y0; y < 32; y += 8)
        t[y][x] = w[(size_t)(kb + y) * N + nb + x];
    __syncthreads();
    #pragma unroll
    for (int y = y0; y < 32; y += 8)
        hi[(size_t)(nb + y) * K + kb + x] = __float2half_rn(t[x][y]);
}

__global__ __launch_bounds__(256) void wtrans_half2(
    const float* __restrict__ w, __half* __restrict__ hi, __half* __restrict__ lo,
    int K, int N)
{
    __shared__ float t[32][33];
    int kb = blockIdx.x * 32, nb = blockIdx.y * 32;
    int x = threadIdx.x & 31, y0 = threadIdx.x >> 5;
    #pragma unroll
    for (int y = y0; y < 32; y += 8)
        t[y][x] = w[(size_t)(kb + y) * N + nb + x];
    __syncthreads();
    #pragma unroll
    for (int y = y0; y < 32; y += 8) {
        float v = t[x][y];
        __half h = __float2half_rn(v);
        hi[(size_t)(nb + y) * K + kb + x] = h;
        lo[(size_t)(nb + y) * K + kb + x] = __float2half_rn(v - __half2float(h));
    }
}

__global__ __launch_bounds__(256) void wtrans_c1(
    const float* __restrict__ w, __half* __restrict__ hi, __half* __restrict__ lo)
{
    int co = threadIdx.x;
    for (int ci = 0; ci < 3; ci++)
        for (int tap = 0; tap < 16; tap++) {
            float v = w[(tap * 3 + ci) * 256 + co];
            __half h = __float2half_rn(v);
            hi[co * 48 + ci * 16 + tap] = h;
            lo[co * 48 + ci * 16 + tap] = __float2half_rn(v - __half2float(h));
        }
}

// ---------------------------------------------------------------------------
// conv1 as 4-term fp16-split mma. M=131072, N=256, K=48 (k = ci*16 + tap).
// Epilogue writes h1 as PRE-SPLIT hi/lo fp16 (bit-identical to the split
// conv2 previously did on the fly).
// ---------------------------------------------------------------------------
__global__ __launch_bounds__(256) void mma_conv1(
    const float* __restrict__ x, const __half* __restrict__ whi,
    const __half* __restrict__ wlo, const float* __restrict__ bias,
    __half* __restrict__ outh, __half* __restrict__ outl)
{
    constexpr int BM = 128, LDAH = 24;
    constexpr int MI = 4, NI = 4;
    constexpr int NS = 3;
    constexpr int TP = BM * LDAH;
    constexpr int STAGE = 4 * TP;

    extern __shared__ __half smh[];
    const uint32_t sbase = smem_u32(smh);

    const int tid = threadIdx.x;
    const int wid = tid >> 5, lid = tid & 31;
    const int g = lid >> 2, t = lid & 3;
    const int wm0 = (wid >> 2) * 64;
    const int wn0 = (wid & 3) * 32;
    const int nblk = blockIdx.x * 128;
    const int mblk = blockIdx.y * BM;

    uint32_t offA[MI], offB[NI];
    #pragma unroll
    for (int mi = 0; mi < MI; mi++) {
        int rowA = wm0 + mi * 16 + ((lid >> 3) & 1) * 8 + (lid & 7);
        int koffA = (lid >> 4) * 8;
        offA[mi] = (uint32_t)(rowA * LDAH + koffA) * 2;
    }
    #pragma unroll
    for (int ni = 0; ni < NI; ni++) {
        int rowB = wn0 + ni * 8 + (lid & 7);
        int koffB = ((lid >> 3) & 1) * 8;
        offB[ni] = (uint32_t)(rowB * LDAH + koffB) * 2;
    }

    const int row = tid >> 1, h = tid & 1;
    const int m = mblk + row;
    const int ox = m % 64, oy = (m / 64) % 64, b = m / 4096;

    float av[8];
    uint4 bFh, bFl;

    auto loadRegs = [&](int ci) {
        #pragma unroll
        for (int kk = 0; kk < 2; kk++) {
            int kh = h * 2 + kk;
            int iy = 2 * oy - 1 + kh;
            #pragma unroll
            for (int kw = 0; kw < 4; kw++) {
                int ix = 2 * ox - 1 + kw;
                float v = 0.f;
                if (iy >= 0 && iy < 128 && ix >= 0 && ix < 128)
                    v = x[((b * 3 + ci) * 128 + iy) * 128 + ix];
                av[kk * 4 + kw] = v;
            }
        }
        bFh = *(const uint4*)&whi[(nblk + row) * 48 + ci * 16 + h * 8];
        bFl = *(const uint4*)&wlo[(nblk + row) * 48 + ci * 16 + h * 8];
    };
    auto storeSmem = [&](int buf) {
        __half* Ahi = smh + buf * STAGE;
        __half* Alo = Ahi + TP;
        __half* Bhi = Alo + TP;
        __half* Blo = Bhi + TP;
        __half hh[8], ll[8];
        #pragma unroll
        for (int j = 0; j < 8; j++) {
            __half hv = __float2half_rn(av[j]);
            hh[j] = hv;
            ll[j] = __float2half_rn(av[j] - __half2float(hv));
        }
        *(uint4*)&Ahi[row * LDAH + h * 8] = *(uint4*)hh;
        *(uint4*)&Alo[row * LDAH + h * 8] = *(uint4*)ll;
        *(uint4*)&Bhi[row * LDAH + h * 8] = bFh;
        *(uint4*)&Blo[row * LDAH + h * 8] = bFl;
    };

    float acc[MI][NI][4];
    #pragma unroll
    for (int mi = 0; mi < MI; mi++)
        #pragma unroll
        for (int ni = 0; ni < NI; ni++)
            #pragma unroll
            for (int c = 0; c < 4; c++) acc[mi][ni][c] = 0.f;

    loadRegs(0);
    storeSmem(0);
    __syncthreads();
    int buf = 0;
    #pragma unroll 1
    for (int s = 0; s < NS; s++) {
        if (s + 1 < NS) loadRegs(s + 1);
        uint32_t AhiB = sbase + (buf * STAGE) * 2;
        uint32_t AloB = AhiB + TP * 2;
        uint32_t BhiB = AloB + TP * 2;
        uint32_t BloB = BhiB + TP * 2;
        uint32_t ah[MI][4], al[MI][4], bh[NI][2], bl[NI][2];
        #pragma unroll
        for (int mi = 0; mi < MI; mi++) {
            ldsm_x4(ah[mi], AhiB + offA[mi]);
            ldsm_x4(al[mi], AloB + offA[mi]);
        }
        #pragma unroll
        for (int ni = 0; ni < NI; ni++) {
            ldsm_x2(bh[ni], BhiB + offB[ni]);
            ldsm_x2(bl[ni], BloB + offB[ni]);
        }
        #pragma unroll
        for (int mi = 0; mi < MI; mi++)
            #pragma unroll
            for (int ni = 0; ni < NI; ni++) {
                mma_f16(acc[mi][ni], ah[mi], bh[ni]);
                mma_f16(acc[mi][ni], ah[mi], bl[ni]);
                mma_f16(acc[mi][ni], al[mi], bh[ni]);
                mma_f16(acc[mi][ni], al[mi], bl[ni]);
            }
        if (s + 1 < NS) {
            storeSmem(buf ^ 1);
            __syncthreads();
            buf ^= 1;
        }
    }

    #pragma unroll
    for (int mi = 0; mi < MI; mi++) {
        #pragma unroll
        for (int half = 0; half < 2; half++) {
            int mo = mblk + wm0 + mi * 16 + g + half * 8;
            #pragma unroll
            for (int ni = 0; ni < NI; ni++) {
                int col = nblk + wn0 + ni * 8 + 2 * t;
                float2 bv = *(const float2*)&bias[col];
                float ox_ = fmaxf(acc[mi][ni][half * 2 + 0] + bv.x, 0.f);
                float oy_ = fmaxf(acc[mi][ni][half * 2 + 1] + bv.y, 0.f);
                __half hx = __float2half_rn(ox_), hy = __float2half_rn(oy_);
                __half lx = __float2half_rn(ox_ - __half2float(hx));
                __half ly = __float2half_rn(oy_ - __half2float(hy));
                __half2 oh = __halves2half2(hx, hy);
                __half2 ol = __halves2half2(lx, ly);
                size_t idx = (size_t)mo * 256 + col;
                *(__half2*)&outh[idx] = oh;
                *(__half2*)&outl[idx] = ol;
            }
        }
    }
}

// ---------------------------------------------------------------------------
// conv2 as 4-term fp16-split mma, BK=16, ldmatrix. A comes PRE-SPLIT from
// conv1 (hi/lo fp16 buffers) — no conversion in the load path.
// ---------------------------------------------------------------------------
template<int Cin, int Cout, int IH, int IW, int OH, int OW>
__global__ __launch_bounds__(256) void mma_conv2(
    const __half* __restrict__ inh, const __half* __restrict__ inl,
    const __half* __restrict__ whi, const __half* __restrict__ wlo,
    const float* __restrict__ bias, float* __restrict__ out)
{
    constexpr int BM = 128, BN = 128, BK = 16, LDAH = 24;
    constexpr int MI = 4, NI = 4;
    constexpr int NCI = Cin / BK;
    constexpr int NS = 16 * NCI;
    constexpr int Ktot = 16 * Cin;
    constexpr int TP = BM * LDAH;
    constexpr int STAGE = 4 * TP;

    extern __shared__ __half smh[];
    const uint32_t sbase = smem_u32(smh);

    const int tid = threadIdx.x;
    const int wid = tid >> 5, lid = tid & 31;
    const int g = lid >> 2, t = lid & 3;
    const int wm0 = (wid >> 2) * 64;
    const int wn0 = (wid & 3) * 32;
    const int nblk = blockIdx.x * BN;
    const int mblk = blockIdx.y * BM;

    uint32_t offA[MI], offB[NI];
    #pragma unroll
    for (int mi = 0; mi < MI; mi++) {
        int rowA = wm0 + mi * 16 + ((lid >> 3) & 1) * 8 + (lid & 7);
        int koffA = (lid >> 4) * 8;
        offA[mi] = (uint32_t)(rowA * LDAH + koffA) * 2;
    }
    #pragma unroll
    for (int ni = 0; ni < NI; ni++) {
        int rowB = wn0 + ni * 8 + (lid & 7);
        int koffB = ((lid >> 3) & 1) * 8;
        offB[ni] = (uint32_t)(rowB * LDAH + koffB) * 2;
    }

    uint4 aFh, aFl, bFh, bFl;

    auto loadRegs = [&](int s) {
        const int tap = s / NCI;
        const int ci0 = (s - tap * NCI) * BK;
        const int kh = tap >> 2, kw = tap & 3;
        const int row = tid >> 1, h8 = tid & 1;
        int m = mblk + row;
        int ox = m % OW; int tmp = m / OW; int oy = tmp % OH; int b = tmp / OH;
        int iy = 2 * oy - 1 + kh, ix = 2 * ox - 1 + kw;
        bool ok = (iy >= 0 && iy < IH && ix >= 0 && ix < IW);
        size_t aidx = (size_t)((b * IH + iy) * IW + ix) * Cin + ci0 + h8 * 8;
        uint4 z = make_uint4(0u, 0u, 0u, 0u);
        aFh = ok ? *(const uint4*)&inh[aidx] : z;
        aFl = ok ? *(const uint4*)&inl[aidx] : z;
        const int kbase = (kh * 4 + kw) * Cin + ci0 + h8 * 8;
        bFh = *(const uint4*)&whi[(size_t)(nblk + row) * Ktot + kbase];
        bFl = *(const uint4*)&wlo[(size_t)(nblk + row) * Ktot + kbase];
    };
    auto storeSmem = [&](int buf) {
        const int row = tid >> 1, h8 = tid & 1;
        __half* Ahi = smh + buf * STAGE;
        __half* Alo = Ahi + TP;
        __half* Bhi = Alo + TP;
        __half* Blo = Bhi + TP;
        *(uint4*)&Ahi[row * LDAH + h8 * 8] = aFh;
        *(uint4*)&Alo[row * LDAH + h8 * 8] = aFl;
        *(uint4*)&Bhi[row * LDAH + h8 * 8] = bFh;
        *(uint4*)&Blo[row * LDAH + h8 * 8] = bFl;
    };

    float acc[MI][NI][4];
    #pragma unroll
    for (int mi = 0; mi < MI; mi++)
        #pragma unroll
        for (int ni = 0; ni < NI; ni++)
            #pragma unroll
            for (int c = 0; c < 4; c++) acc[mi][ni][c] = 0.f;

    loadRegs(0);
    storeSmem(0);
    __syncthreads();
    int buf = 0;
    #pragma unroll 1
    for (int s = 0; s < NS; s++) {
        if (s + 1 < NS) loadRegs(s + 1);
        uint32_t AhiB = sbase + (buf * STAGE) * 2;
        uint32_t AloB = AhiB + TP * 2;
        uint32_t BhiB = AloB + TP * 2;
        uint32_t BloB = BhiB + TP * 2;
        uint32_t ah[MI][4], al[MI][4], bh[NI][2], bl[NI][2];
        #pragma unroll
        for (int mi = 0; mi < MI; mi++) {
            ldsm_x4(ah[mi], AhiB + offA[mi]);
            ldsm_x4(al[mi], AloB + offA[mi]);
        }
        #pragma unroll
        for (int ni = 0; ni < NI; ni++) {
            ldsm_x2(bh[ni], BhiB + offB[ni]);
            ldsm_x2(bl[ni], BloB + offB[ni]);
        }
        #pragma unroll
        for (int mi = 0; mi < MI; mi++)
            #pragma unroll
            for (int ni = 0; ni < NI; ni++) {
                mma_f16(acc[mi][ni], ah[mi], bh[ni]);
                mma_f16(acc[mi][ni], ah[mi], bl[ni]);
                mma_f16(acc[mi][ni], al[mi], bh[ni]);
                mma_f16(acc[mi][ni], al[mi], bl[ni]);
            }
        if (s + 1 < NS) {
            storeSmem(buf ^ 1);
            __syncthreads();
            buf ^= 1;
        }
    }

    #pragma unroll
    for (int mi = 0; mi < MI; mi++) {
        #pragma unroll
        for (int half = 0; half < 2; half++) {
            int m = mblk + wm0 + mi * 16 + g + half * 8;
            #pragma unroll
            for (int ni = 0; ni < NI; ni++) {
                int col = nblk + wn0 + ni * 8 + 2 * t;
                float2 bv = *(const float2*)&bias[col];
                float2 o;
                o.x = fmaxf(acc[mi][ni][half * 2 + 0] + bv.x, 0.f);
                o.y = fmaxf(acc[mi][ni][half * 2 + 1] + bv.y, 0.f);
                *(float2*)&out[(size_t)m * Cout + col] = o;
            }
        }
    }
}

// ---------------------------------------------------------------------------
// conv3: exact fp32 SIMT implicit GEMM, split-K x8 (argmin-critical; exact).
// ---------------------------------------------------------------------------
template<int BM, int BN, int BK, int TM, int TN,
         int Cin, int Cout, int IH, int IW, int OH, int OW, int KSPLIT>
__global__ __launch_bounds__(256) void conv_s2_gemm(
    const float* __restrict__ in, const float* __restrict__ w,
    const float* __restrict__ bias, float* __restrict__ out)
{
    static_assert((BM / TM) * (BN / TN) == 256, "thread count");
    constexpr int NCI   = Cin / BK;
    constexpr int NS    = 16 * NCI;
    constexpr int NSC   = NS / KSPLIT;
    constexpr int MTOT  = 32 * OH * OW;
    constexpr int ALOOP = (BM * BK / 4) / 256;
    constexpr int BLOOP = (BK * BN / 4) / 256;
    static_assert(ALOOP >= 1 && BLOOP >= 1, "load split");
    static_assert(NSC >= 2, "pipeline");

    __shared__ __align__(16) float As[2][BK][BM + 4];
    __shared__ __align__(16) float Bs[2][BK][BN + 4];

    const int tid  = threadIdx.x;
    const int mblk = blockIdx.y * BM;
    const int kc   = (KSPLIT > 1) ? (int)blockIdx.x : 0;
    const int nblk = (KSPLIT > 1) ? 0 : blockIdx.x * BN;

    float4 areg[ALOOP], breg[BLOOP];

    auto loadRegs = [&](int s) {
        int t16 = s / NCI;
        int ci0 = (s % NCI) * BK;
        int kh = t16 >> 2, kw = t16 & 3;
        #pragma unroll
        for (int i = 0; i < ALOOP; i++) {
            int idx = tid + i * 256;
            int row = idx / (BK / 4);
            int c4  = idx % (BK / 4);
            int m   = mblk + row;
            int ox  = m % OW;
            int tmp = m / OW;
            int oy  = tmp % OH;
            int b   = tmp / OH;
            int iy  = 2 * oy - 1 + kh;
            int ix  = 2 * ox - 1 + kw;
            if (iy >= 0 && iy < IH && ix >= 0 && ix < IW)
                areg[i] = *(const float4*)&in[((b * IH + iy) * IW + ix) * Cin + ci0 + c4 * 4];
            else
                areg[i] = make_float4(0.f, 0.f, 0.f, 0.f);
        }
        #pragma unroll
        for (int i = 0; i < BLOOP; i++) {
            int idx  = tid + i * 256;
            int krow = idx / (BN / 4);
            int c4   = idx % (BN / 4);
            breg[i] = *(const float4*)&w[(t16 * Cin + ci0 + krow) * Cout + nblk + c4 * 4];
        }
    };
    auto storeSmem = [&](int buf) {
        #pragma unroll
        for (int i = 0; i < ALOOP; i++) {
            int idx = tid + i * 256;
            int row = idx / (BK / 4);
            int c4  = idx % (BK / 4);
            As[buf][c4 * 4 + 0][row] = areg[i].x;
            As[buf][c4 * 4 + 1][row] = areg[i].y;
            As[buf][c4 * 4 + 2][row] = areg[i].z;
            As[buf][c4 * 4 + 3][row] = areg[i].w;
        }
        #pragma unroll
        for (int i = 0; i < BLOOP; i++) {
            int idx  = tid + i * 256;
            int krow = idx / (BN / 4);
            int c4   = idx % (BN / 4);
            *(float4*)&Bs[buf][krow][c4 * 4] = breg[i];
        }
    };

    const int ty = tid / (BN / TN);
    const int tx = tid % (BN / TN);
    float acc[TM][TN];
    #pragma unroll
    for (int i = 0; i < TM; i++)
        #pragma unroll
        for (int j = 0; j < TN; j++) acc[i][j] = 0.f;

    const int s0 = kc * NSC;
    loadRegs(s0);
    storeSmem(0);
    __syncthreads();
    int buf = 0;
    for (int s = s0; s < s0 + NSC; s++) {
        if (s + 1 < s0 + NSC) loadRegs(s + 1);
        #pragma unroll
        for (int kk = 0; kk < BK; kk++) {
            float a[TM], bb[TN];
            #pragma unroll
            for (int i = 0; i < TM; i += 4)
                *(float4*)&a[i] = *(const float4*)&As[buf][kk][ty * TM + i];
            #pragma unroll
            for (int j = 0; j < TN; j += 4)
                *(float4*)&bb[j] = *(const float4*)&Bs[buf][kk][tx * TN + j];
            #pragma unroll
            for (int i = 0; i < TM; i++)
                #pragma unroll
                for (int j = 0; j < TN; j++)
                    acc[i][j] = fmaf(a[i], bb[j], acc[i][j]);
        }
        if (s + 1 < s0 + NSC) {
            storeSmem(buf ^ 1);
            __syncthreads();
            buf ^= 1;
        }
    }
    #pragma unroll
    for (int i = 0; i < TM; i++) {
        int m = mblk + ty * TM + i;
        #pragma unroll
        for (int j = 0; j < TN; j++) {
            int n = nblk + tx * TN + j;
            if (KSPLIT > 1) {
                out[(size_t)kc * MTOT * Cout + (size_t)m * Cout + n] = acc[i][j];
            } else {
                float v = acc[i][j] + bias[n];
                out[(size_t)m * Cout + n] = fmaxf(v, 0.f);
            }
        }
    }
}

__global__ __launch_bounds__(256) void reduce_z_kernel(const float* __restrict__ bias) {
    int i = blockIdx.x * 256 + threadIdx.x;
    float s = 0.f;
    #pragma unroll
    for (int kc = 0; kc < 8; kc++)
        s += g_zpart[kc * 8192 * 64 + i];
    g_z[i] = fmaxf(s + bias[i & 63], 0.f);
}

// ---------------------------------------------------------------------------
// Decoder transposed conv: fp16 mma with ldmatrix frag loads (128x128 tiles).
// ---------------------------------------------------------------------------
template<int BM, int BN, int WARPS_M, int WARPS_N, int Cin, int Cout,
         int ISP, int OSP>
__global__ __launch_bounds__(256) void mma_deconv(
    const float* __restrict__ in, const __half* __restrict__ wth,
    const float* __restrict__ bias, float* __restrict__ out)
{
    constexpr int BK = 16, LDAH = 24;
    constexpr int WM = BM / WARPS_M, WN = BN / WARPS_N;
    constexpr int MI = WM / 16, NI = WN / 8;
    constexpr int NCI = Cin / BK;
    constexpr int NS = 4 * NCI;
    constexpr int Ktot = 16 * Cin;
    constexpr int ALOOP = (BM * 4) / 256;
    constexpr int APITCH = BM * LDAH;
    constexpr int BPITCH = BN * LDAH;
    static_assert(WARPS_M * WARPS_N == 8, "8 warps");
    static_assert(ALOOP >= 1, "load split");
    static_assert(BN * 2 == 256, "B load mapping");

    extern __shared__ __half smh[];
    __half* Abase = smh;
    __half* Bbase = smh + 2 * APITCH;
    const uint32_t sbase = smem_u32(smh);

    const int tid = threadIdx.x;
    const int wid = tid >> 5, lid = tid & 31;
    const int g = lid >> 2, t = lid & 3;
    const int wm0 = (wid / WARPS_N) * WM;
    const int wn0 = (wid % WARPS_N) * WN;
    const int nblk = blockIdx.x * BN;
    const int mblk = blockIdx.y * BM;
    const int par  = blockIdx.z;
    const int py = par >> 1, px = par & 1;

    uint32_t offA[MI], offB[NI];
    #pragma unroll
    for (int mi = 0; mi < MI; mi++) {
        int rowA = wm0 + mi * 16 + ((lid >> 3) & 1) * 8 + (lid & 7);
        int koffA = (lid >> 4) * 8;
        offA[mi] = (uint32_t)(rowA * LDAH + koffA) * 2;
    }
    #pragma unroll
    for (int ni = 0; ni < NI; ni++) {
        int rowB = wn0 + ni * 8 + (lid & 7);
        int koffB = ((lid >> 3) & 1) * 8;
        offB[ni] = (uint32_t)(rowB * LDAH + koffB) * 2;
    }

    float4 aF[ALOOP];
    uint4  bF;

    auto loadRegs = [&](int s) {
        const int tap = s / NCI;
        const int ci0 = (s - tap * NCI) * BK;
        int tyk = tap >> 1, txk = tap & 1;
        int kh = (py ? 2 : 3) - 2 * tyk;
        int kw = (px ? 2 : 3) - 2 * txk;
        #pragma unroll
        for (int i = 0; i < ALOOP; i++) {
            int slot = tid + i * 256;
            int row = slot >> 2, c4 = slot & 3;
            int m = mblk + row;
            int mx = m % ISP; int t2 = m / ISP; int my = t2 % ISP; int b = t2 / ISP;
            int iy = my + tyk - 1 + py;
            int ix = mx + txk - 1 + px;
            bool ok = (iy >= 0 && iy < ISP && ix >= 0 && ix < ISP);
            aF[i] = ok ? *(const float4*)&in[(size_t)((b * ISP + iy) * ISP + ix) * Cin + ci0 + c4 * 4]
                       : make_float4(0.f, 0.f, 0.f, 0.f);
        }
        const int kbase = (kh * 4 + kw) * Cin + ci0;
        {
            int row = tid >> 1, h8 = tid & 1;
            bF = *(const uint4*)&wth[(size_t)(nblk + row) * Ktot + kbase + h8 * 8];
        }
    };
    auto storeSmem = [&](int buf) {
        #pragma unroll
        for (int i = 0; i < ALOOP; i++) {
            int slot = tid + i * 256;
            int row = slot >> 2, c4 = slot & 3;
            float4 v = aF[i];
            __half2 p0 = __floats2half2_rn(v.x, v.y);
            __half2 p1 = __floats2half2_rn(v.z, v.w);
            uint2 st;
            st.x = *(uint32_t*)&p0;
            st.y = *(uint32_t*)&p1;
            *(uint2*)&Abase[buf * APITCH + row * LDAH + c4 * 4] = st;
        }
        {
            int row = tid >> 1, h8 = tid & 1;
            *(uint4*)&Bbase[buf * BPITCH + row * LDAH + h8 * 8] = bF;
        }
    };

    float acc[MI][NI][4];
    #pragma unroll
    for (int mi = 0; mi < MI; mi++)
        #pragma unroll
        for (int ni = 0; ni < NI; ni++)
            #pragma unroll
            for (int c = 0; c < 4; c++) acc[mi][ni][c] = 0.f;

    loadRegs(0);
    storeSmem(0);
    __syncthreads();
    int buf = 0;
    #pragma unroll 1
    for (int s = 0; s < NS; s++) {
        if (s + 1 < NS) loadRegs(s + 1);
        uint32_t AB = sbase + (buf * APITCH) * 2;
        uint32_t BB = sbase + (2 * APITCH + buf * BPITCH) * 2;
        uint32_t au[MI][4], bu[NI][2];
        #pragma unroll
        for (int mi = 0; mi < MI; mi++)
            ldsm_x4(au[mi], AB + offA[mi]);
        #pragma unroll
        for (int ni = 0; ni < NI; ni++)
            ldsm_x2(bu[ni], BB + offB[ni]);
        #pragma unroll
        for (int mi = 0; mi < MI; mi++)
            #pragma unroll
            for (int ni = 0; ni < NI; ni++)
                mma_f16(acc[mi][ni], au[mi], bu[ni]);
        if (s + 1 < NS) {
            storeSmem(buf ^ 1);
            __syncthreads();
            buf ^= 1;
        }
    }

    #pragma unroll
    for (int mi = 0; mi < MI; mi++) {
        #pragma unroll
        for (int half = 0; half < 2; half++) {
            int m = mblk + wm0 + mi * 16 + g + half * 8;
            int mx = m % ISP; int t2 = m / ISP; int my = t2 % ISP; int b = t2 / ISP;
            size_t obase = ((size_t)(b * OSP + 2 * my + py) * OSP + 2 * mx + px) * Cout;
            #pragma unroll
            for (int ni = 0; ni < NI; ni++) {
                int col = nblk + wn0 + ni * 8 + 2 * t;
                float2 bv = *(const float2*)&bias[col];
                float2 o;
                o.x = fmaxf(acc[mi][ni][half * 2 + 0] + bv.x, 0.f);
                o.y = fmaxf(acc[mi][ni][half * 2 + 1] + bv.y, 0.f);
                *(float2*)&out[obase + col] = o;
            }
        }
    }
}

// ---------------------------------------------------------------------------
// VQ: 8 lane-groups per pixel over 64 codes each; shfl argmin reduce with
// first-index tie rule. Exact fp32.
// ---------------------------------------------------------------------------
__global__ __launch_bounds__(256) void vq_kernel(const float* __restrict__ cb) {
    const int lid = threadIdx.x & 31, wrp = threadIdx.x >> 5;
    const int pixw = lid & 3, grp = lid >> 2;
    const int p = blockIdx.x * 32 + wrp * 4 + pixw;

    float z[64];
    const float4* zp = (const float4*)&g_z[p * 64];
    #pragma unroll
    for (int j4 = 0; j4 < 16; j4++) {
        float4 v = zp[j4];
        z[j4 * 4 + 0] = v.x; z[j4 * 4 + 1] = v.y;
        z[j4 * 4 + 2] = v.z; z[j4 * 4 + 3] = v.w;
    }
    float best = 3.4e38f;
    int bi = 0;
    for (int c = grp * 64; c < grp * 64 + 64; c++) {
        const float4* cp = (const float4*)&cb[c * 64];
        float dot = 0.f;
        #pragma unroll
        for (int j4 = 0; j4 < 16; j4++) {
            float4 v = __ldg(&cp[j4]);
            dot = fmaf(z[j4 * 4 + 0], v.x, dot);
            dot = fmaf(z[j4 * 4 + 1], v.y, dot);
            dot = fmaf(z[j4 * 4 + 2], v.z, dot);
            dot = fmaf(z[j4 * 4 + 3], v.w, dot);
        }
        float d = g_cnorm[c] - 2.f * dot;
        if (d < best) { best = d; bi = c; }
    }
    #pragma unroll
    for (int off = 4; off <= 16; off <<= 1) {
        float ob = __shfl_xor_sync(0xFFFFFFFFu, best, off);
        int  obi = __shfl_xor_sync(0xFFFFFFFFu, bi,   off);
        if (ob < best || (ob == best && obi < bi)) { best = ob; bi = obi; }
    }

    float ls = 0.f;
    if (grp == 0) {
        float4* qp = (float4*)&g_q[p * 64];
        const float4* cbest = (const float4*)&cb[bi * 64];
        #pragma unroll
        for (int j4 = 0; j4 < 16; j4++) {
            float4 v = cbest[j4];
            qp[j4] = v;
            float d0 = z[j4 * 4 + 0] - v.x;
            float d1 = z[j4 * 4 + 1] - v.y;
            float d2 = z[j4 * 4 + 2] - v.z;
            float d3 = z[j4 * 4 + 3] - v.w;
            ls = fmaf(d0, d0, ls); ls = fmaf(d1, d1, ls);
            ls = fmaf(d2, d2, ls); ls = fmaf(d3, d3, ls);
        }
        g_used[bi] = 1;
    }

    __shared__ float red[256];
    red[threadIdx.x] = ls;
    __syncthreads();
    for (int s2 = 128; s2 > 0; s2 >>= 1) {
        if (threadIdx.x < s2) red[threadIdx.x] += red[threadIdx.x + s2];
        __syncthreads();
    }
    if (threadIdx.x == 0) g_partial[blockIdx.x] = red[0];
}

// ---------------------------------------------------------------------------
// deconv3: 256->3, sigmoid, NHWC in -> NCHW out (exact). 2 rows per block.
// ---------------------------------------------------------------------------
__global__ __launch_bounds__(256) void deconv3_kernel(
    const float* __restrict__ in, const float* __restrict__ w,
    const float* __restrict__ bias, float* __restrict__ out)
{
    __shared__ float ws[16 * 3 * 256];   // [tap][c][ci]
    for (int i = threadIdx.x; i < 16 * 3 * 256; i += 256) {
        int tap = i / 768;
        int rem = i - tap * 768;
        int c = rem >> 8;
        int ci = rem & 255;
        ws[i] = w[(tap * 256 + ci) * 3 + c];
    }
    __syncthreads();

    int b  = blockIdx.x >> 6;
    int oy = ((blockIdx.x & 63) << 1) | (threadIdx.x >> 7);
    int ox = threadIdx.x & 127;
    int py = oy & 1, px = ox & 1;
    int my = oy >> 1, mx = ox >> 1;

    float acc0 = bias[0], acc1 = bias[1], acc2 = bias[2];
    #pragma unroll
    for (int t = 0; t < 4; t++) {
        int tyk = t >> 1, txk = t & 1;
        int iy = my + tyk - 1 + py;
        int ix = mx + txk - 1 + px;
        if (iy < 0 || iy >= 64 || ix < 0 || ix >= 64) continue;
        int kh = (py ? 2 : 3) - 2 * tyk;
        int kw = (px ? 2 : 3) - 2 * txk;
        const float* ip  = &in[((b * 64 + iy) * 64 + ix) * 256];
        const float* wp0 = &ws[((kh * 4 + kw) * 3 + 0) * 256];
        const float* wp1 = &ws[((kh * 4 + kw) * 3 + 1) * 256];
        const float* wp2 = &ws[((kh * 4 + kw) * 3 + 2) * 256];
        #pragma unroll 8
        for (int ci = 0; ci < 256; ci += 4) {
            float4 v  = *(const float4*)&ip[ci];
            float4 w0 = *(const float4*)&wp0[ci];
            float4 w1 = *(const float4*)&wp1[ci];
            float4 w2 = *(const float4*)&wp2[ci];
            acc0 = fmaf(v.x, w0.x, acc0);
            acc1 = fmaf(v.x, w1.x, acc1);
            acc2 = fmaf(v.x, w2.x, acc2);
            acc0 = fmaf(v.y, w0.y, acc0);
            acc1 = fmaf(v.y, w1.y, acc1);
            acc2 = fmaf(v.y, w2.y, acc2);
            acc0 = fmaf(v.z, w0.z, acc0);
            acc1 = fmaf(v.z, w1.z, acc1);
            acc2 = fmaf(v.z, w2.z, acc2);
            acc0 = fmaf(v.w, w0.w, acc0);
            acc1 = fmaf(v.w, w1.w, acc1);
            acc2 = fmaf(v.w, w2.w, acc2);
        }
    }
    out[((b * 3 + 0) * 128 + oy) * 128 + ox] = 1.f / (1.f + expf(-acc0));
    out[((b * 3 + 1) * 128 + oy) * 128 + ox] = 1.f / (1.f + expf(-acc1));
    out[((b * 3 + 2) * 128 + oy) * 128 + ox] = 1.f / (1.f + expf(-acc2));
}

__global__ void finalize_kernel(float* __restrict__ out, int out_size) {
    __shared__ int total;
    int t = threadIdx.x;
    if (t == 0) total = 0;
    __syncthreads();
    if (t < 512 && g_used[t]) atomicAdd(&total, 1);
    __syncthreads();
    if (t == 0) {
        float sum = 0.f;
        for (int i = 0; i < 256; i++) sum += g_partial[i];
        float mean = sum / (float)(8192 * 64);
        out[out_size - 3] = mean;
        out[out_size - 2] = mean;
        out[out_size - 1] = (float)total;
    }
}

// ---------------------------------------------------------------------------
extern "C" void kernel_launch(void* const* d_in, const int* in_sizes, int n_in,
                              void* d_out, int out_size)
{
    const float* x   = (const float*)d_in[0];
    const float* ew1 = (const float*)d_in[1];
    const float* eb1 = (const float*)d_in[2];
    const float* ew2 = (const float*)d_in[3];
    const float* eb2 = (const float*)d_in[4];
    const float* ew3 = (const float*)d_in[5];
    const float* eb3 = (const float*)d_in[6];
    const float* cb  = (const float*)d_in[7];
    const float* dw1 = (const float*)d_in[8];
    const float* db1 = (const float*)d_in[9];
    const float* dw2 = (const float*)d_in[10];
    const float* db2 = (const float*)d_in[11];
    const float* dw3 = (const float*)d_in[12];
    const float* db3 = (const float*)d_in[13];
    float* out = (float*)d_out;

    float *h2, *zpart, *q, *d1, *d2;
    __half *h1h, *h1l, *we1h, *we1l, *we2h, *we2l, *wd1h, *wd2h;
    cudaGetSymbolAddress((void**)&h1h, g_h1h);
    cudaGetSymbolAddress((void**)&h1l, g_h1l);
    cudaGetSymbolAddress((void**)&h2, g_h2);
    cudaGetSymbolAddress((void**)&zpart, g_zpart);
    cudaGetSymbolAddress((void**)&q,  g_q);
    cudaGetSymbolAddress((void**)&d1, g_d1);
    cudaGetSymbolAddress((void**)&d2, g_d2);
    cudaGetSymbolAddress((void**)&we1h, g_we1h);
    cudaGetSymbolAddress((void**)&we1l, g_we1l);
    cudaGetSymbolAddress((void**)&we2h, g_we2h);
    cudaGetSymbolAddress((void**)&we2l, g_we2l);
    cudaGetSymbolAddress((void**)&wd1h, g_wd1h);
    cudaGetSymbolAddress((void**)&wd2h, g_wd2h);

    const int SM_DEC = 2 * (128 * 24 + 128 * 24) * 2;   // 24576 B
    const int SM_MMA = 2 * 4 * 128 * 24 * 2;            // 49152 B
    cudaFuncSetAttribute(mma_conv1,
                         cudaFuncAttributeMaxDynamicSharedMemorySize, SM_MMA);
    cudaFuncSetAttribute(mma_conv2<256, 512, 64, 64, 32, 32>,
                         cudaFuncAttributeMaxDynamicSharedMemorySize, SM_MMA);

    cnorm_kernel<<<2, 256>>>(cb);

    // weight prep
    wtrans_c1<<<1, 256>>>(ew1, we1h, we1l);
    wtrans_half2<<<dim3(4096 / 32, 512 / 32), 256>>>(ew2, we2h, we2l, 4096, 512);
    wtrans_half<<<dim3(1024 / 32, 512 / 32), 256>>>(dw1, wd1h, 1024, 512);
    wtrans_half<<<dim3(8192 / 32, 256 / 32), 256>>>(dw2, wd2h, 8192, 256);

    // encoder
    mma_conv1<<<dim3(2, 1024), 256, SM_MMA>>>(x, we1h, we1l, eb1, h1h, h1l);
    mma_conv2<256, 512, 64, 64, 32, 32>
        <<<dim3(4, 256), 256, SM_MMA>>>(h1h, h1l, we2h, we2l, eb2, h2);
    conv_s2_gemm<128, 64, 16, 8, 4, 512, 64, 32, 32, 16, 16, 8>
        <<<dim3(8, 64), 256>>>(h2, ew3, eb3, zpart);
    reduce_z_kernel<<<2048, 256>>>(eb3);

    // vector quantize (exact)
    vq_kernel<<<256, 256>>>(cb);

    // decoder (fp16 tensor, ldmatrix)
    mma_deconv<128, 128, 2, 4, 64, 512, 16, 32>
        <<<dim3(4, 64, 4), 256, SM_DEC>>>(q, wd1h, db1, d1);
    mma_deconv<128, 128, 2, 4, 512, 256, 32, 64>
        <<<dim3(2, 256, 4), 256, SM_DEC>>>(d1, wd2h, db2, d2);
    deconv3_kernel<<<32 * 64, 256>>>(d2, dw3, db3, out);

    finalize_kernel<<<1, 512>>>(out, out_size);
}

// round 16
// speedup vs baseline: 1.1308x; 1.0151x over previous
#include <cuda_runtime.h>
#include <cuda_fp16.h>
#include <math.h>
#include <stdint.h>

// ===========================================================================
// VQ-VAE forward.  (R15 + d1 stored as fp16: pre-split producer pattern
// applied to the deconv1 -> deconv2 seam; bit-identical by construction.)
// conv1+conv2: fp16 4-term split mma (one split GEMM pre-VQ argmin-safe;
// stacking a second (conv3) flips argmin -> conv3 stays exact fp32).
// conv3: exact fp32 SIMT split-K x8. VQ exact fp32.
// Decoder deconv1/2: fp16 mma + ldmatrix, 128x128 tiles (err ~1.3e-4).
// ===========================================================================

__device__ __align__(256) __half g_h1h[32 * 64 * 64 * 256];
__device__ __align__(256) __half g_h1l[32 * 64 * 64 * 256];
__device__ float g_h2[32 * 32 * 32 * 512];
__device__ float g_zpart[8 * 8192 * 64];
__device__ float g_z [32 * 16 * 16 * 64];
__device__ float g_q [32 * 16 * 16 * 64];
__device__ __align__(256) __half g_d1h[32 * 32 * 32 * 512];
__device__ float g_d2[32 * 64 * 64 * 256];
__device__ float g_cnorm[512];
__device__ float g_partial[256];
__device__ int   g_used[512];
__device__ __align__(256) __half g_we1h[256 * 48],  g_we1l[256 * 48];
__device__ __align__(256) __half g_we2h[512 * 4096], g_we2l[512 * 4096];
__device__ __align__(256) __half g_wd1h[512 * 1024];
__device__ __align__(256) __half g_wd2h[256 * 8192];

__device__ __forceinline__ void mma_f16(float* c, const uint32_t* a, const uint32_t* b) {
    asm volatile(
        "mma.sync.aligned.m16n8k16.row.col.f32.f16.f16.f32 "
        "{%0,%1,%2,%3}, {%4,%5,%6,%7}, {%8,%9}, {%0,%1,%2,%3};"
        : "+f"(c[0]), "+f"(c[1]), "+f"(c[2]), "+f"(c[3])
        : "r"(a[0]), "r"(a[1]), "r"(a[2]), "r"(a[3]), "r"(b[0]), "r"(b[1]));
}
__device__ __forceinline__ void ldsm_x4(uint32_t* r, uint32_t addr) {
    asm volatile("ldmatrix.sync.aligned.m8n8.x4.shared.b16 {%0,%1,%2,%3}, [%4];"
        : "=r"(r[0]), "=r"(r[1]), "=r"(r[2]), "=r"(r[3]) : "r"(addr));
}
__device__ __forceinline__ void ldsm_x2(uint32_t* r, uint32_t addr) {
    asm volatile("ldmatrix.sync.aligned.m8n8.x2.shared.b16 {%0,%1}, [%2];"
        : "=r"(r[0]), "=r"(r[1]) : "r"(addr));
}
__device__ __forceinline__ uint32_t smem_u32(const void* p) {
    return (uint32_t)__cvta_generic_to_shared(p);
}

// ---------------------------------------------------------------------------
__global__ void cnorm_kernel(const float* __restrict__ cb) {
    int c = blockIdx.x * blockDim.x + threadIdx.x;
    if (c < 512) {
        float s = 0.f;
        #pragma unroll 8
        for (int j = 0; j < 64; j++) {
            float v = cb[c * 64 + j];
            s = fmaf(v, v, s);
        }
        g_cnorm[c] = s;
        g_used[c] = 0;
    }
}

__global__ __launch_bounds__(256) void wtrans_half(
    const float* __restrict__ w, __half* __restrict__ hi, int K, int N)
{
    __shared__ float t[32][33];
    int kb = blockIdx.x * 32, nb = blockIdx.y * 32;
    int x = threadIdx.x & 31, y0 = threadIdx.x >> 5;
    #pragma unroll
    for (int y = y0; y < 32; y += 8)
        t[y][x] = w[(size_t)(kb + y) * N + nb + x];
    __syncthreads();
    #pragma unroll
    for (int y = y0; y < 32; y += 8)
        hi[(size_t)(nb + y) * K + kb + x] = __float2half_rn(t[x][y]);
}

__global__ __launch_bounds__(256) void wtrans_half2(
    const float* __restrict__ w, __half* __restrict__ hi, __half* __restrict__ lo,
    int K, int N)
{
    __shared__ float t[32][33];
    int kb = blockIdx.x * 32, nb = blockIdx.y * 32;
    int x = threadIdx.x & 31, y0 = threadIdx.x >> 5;
    #pragma unroll
    for (int y = y0; y < 32; y += 8)
        t[y][x] = w[(size_t)(kb + y) * N + nb + x];
    __syncthreads();
    #pragma unroll
    for (int y = y0; y < 32; y += 8) {
        float v = t[x][y];
        __half h = __float2half_rn(v);
        hi[(size_t)(nb + y) * K + kb + x] = h;
        lo[(size_t)(nb + y) * K + kb + x] = __float2half_rn(v - __half2float(h));
    }
}

__global__ __launch_bounds__(256) void wtrans_c1(
    const float* __restrict__ w, __half* __restrict__ hi, __half* __restrict__ lo)
{
    int co = threadIdx.x;
    for (int ci = 0; ci < 3; ci++)
        for (int tap = 0; tap < 16; tap++) {
            float v = w[(tap * 3 + ci) * 256 + co];
            __half h = __float2half_rn(v);
            hi[co * 48 + ci * 16 + tap] = h;
            lo[co * 48 + ci * 16 + tap] = __float2half_rn(v - __half2float(h));
        }
}

// ---------------------------------------------------------------------------
// conv1 as 4-term fp16-split mma. M=131072, N=256, K=48 (k = ci*16 + tap).
// Epilogue writes h1 PRE-SPLIT hi/lo fp16.
// ---------------------------------------------------------------------------
__global__ __launch_bounds__(256) void mma_conv1(
    const float* __restrict__ x, const __half* __restrict__ whi,
    const __half* __restrict__ wlo, const float* __restrict__ bias,
    __half* __restrict__ outh, __half* __restrict__ outl)
{
    constexpr int BM = 128, LDAH = 24;
    constexpr int MI = 4, NI = 4;
    constexpr int NS = 3;
    constexpr int TP = BM * LDAH;
    constexpr int STAGE = 4 * TP;

    extern __shared__ __half smh[];
    const uint32_t sbase = smem_u32(smh);

    const int tid = threadIdx.x;
    const int wid = tid >> 5, lid = tid & 31;
    const int g = lid >> 2, t = lid & 3;
    const int wm0 = (wid >> 2) * 64;
    const int wn0 = (wid & 3) * 32;
    const int nblk = blockIdx.x * 128;
    const int mblk = blockIdx.y * BM;

    uint32_t offA[MI], offB[NI];
    #pragma unroll
    for (int mi = 0; mi < MI; mi++) {
        int rowA = wm0 + mi * 16 + ((lid >> 3) & 1) * 8 + (lid & 7);
        int koffA = (lid >> 4) * 8;
        offA[mi] = (uint32_t)(rowA * LDAH + koffA) * 2;
    }
    #pragma unroll
    for (int ni = 0; ni < NI; ni++) {
        int rowB = wn0 + ni * 8 + (lid & 7);
        int koffB = ((lid >> 3) & 1) * 8;
        offB[ni] = (uint32_t)(rowB * LDAH + koffB) * 2;
    }

    const int row = tid >> 1, h = tid & 1;
    const int m = mblk + row;
    const int ox = m % 64, oy = (m / 64) % 64, b = m / 4096;

    float av[8];
    uint4 bFh, bFl;

    auto loadRegs = [&](int ci) {
        #pragma unroll
        for (int kk = 0; kk < 2; kk++) {
            int kh = h * 2 + kk;
            int iy = 2 * oy - 1 + kh;
            #pragma unroll
            for (int kw = 0; kw < 4; kw++) {
                int ix = 2 * ox - 1 + kw;
                float v = 0.f;
                if (iy >= 0 && iy < 128 && ix >= 0 && ix < 128)
                    v = x[((b * 3 + ci) * 128 + iy) * 128 + ix];
                av[kk * 4 + kw] = v;
            }
        }
        bFh = *(const uint4*)&whi[(nblk + row) * 48 + ci * 16 + h * 8];
        bFl = *(const uint4*)&wlo[(nblk + row) * 48 + ci * 16 + h * 8];
    };
    auto storeSmem = [&](int buf) {
        __half* Ahi = smh + buf * STAGE;
        __half* Alo = Ahi + TP;
        __half* Bhi = Alo + TP;
        __half* Blo = Bhi + TP;
        __half hh[8], ll[8];
        #pragma unroll
        for (int j = 0; j < 8; j++) {
            __half hv = __float2half_rn(av[j]);
            hh[j] = hv;
            ll[j] = __float2half_rn(av[j] - __half2float(hv));
        }
        *(uint4*)&Ahi[row * LDAH + h * 8] = *(uint4*)hh;
        *(uint4*)&Alo[row * LDAH + h * 8] = *(uint4*)ll;
        *(uint4*)&Bhi[row * LDAH + h * 8] = bFh;
        *(uint4*)&Blo[row * LDAH + h * 8] = bFl;
    };

    float acc[MI][NI][4];
    #pragma unroll
    for (int mi = 0; mi < MI; mi++)
        #pragma unroll
        for (int ni = 0; ni < NI; ni++)
            #pragma unroll
            for (int c = 0; c < 4; c++) acc[mi][ni][c] = 0.f;

    loadRegs(0);
    storeSmem(0);
    __syncthreads();
    int buf = 0;
    #pragma unroll 1
    for (int s = 0; s < NS; s++) {
        if (s + 1 < NS) loadRegs(s + 1);
        uint32_t AhiB = sbase + (buf * STAGE) * 2;
        uint32_t AloB = AhiB + TP * 2;
        uint32_t BhiB = AloB + TP * 2;
        uint32_t BloB = BhiB + TP * 2;
        uint32_t ah[MI][4], al[MI][4], bh[NI][2], bl[NI][2];
        #pragma unroll
        for (int mi = 0; mi < MI; mi++) {
            ldsm_x4(ah[mi], AhiB + offA[mi]);
            ldsm_x4(al[mi], AloB + offA[mi]);
        }
        #pragma unroll
        for (int ni = 0; ni < NI; ni++) {
            ldsm_x2(bh[ni], BhiB + offB[ni]);
            ldsm_x2(bl[ni], BloB + offB[ni]);
        }
        #pragma unroll
        for (int mi = 0; mi < MI; mi++)
            #pragma unroll
            for (int ni = 0; ni < NI; ni++) {
                mma_f16(acc[mi][ni], ah[mi], bh[ni]);
                mma_f16(acc[mi][ni], ah[mi], bl[ni]);
                mma_f16(acc[mi][ni], al[mi], bh[ni]);
                mma_f16(acc[mi][ni], al[mi], bl[ni]);
            }
        if (s + 1 < NS) {
            storeSmem(buf ^ 1);
            __syncthreads();
            buf ^= 1;
        }
    }

    #pragma unroll
    for (int mi = 0; mi < MI; mi++) {
        #pragma unroll
        for (int half = 0; half < 2; half++) {
            int mo = mblk + wm0 + mi * 16 + g + half * 8;
            #pragma unroll
            for (int ni = 0; ni < NI; ni++) {
                int col = nblk + wn0 + ni * 8 + 2 * t;
                float2 bv = *(const float2*)&bias[col];
                float ox_ = fmaxf(acc[mi][ni][half * 2 + 0] + bv.x, 0.f);
                float oy_ = fmaxf(acc[mi][ni][half * 2 + 1] + bv.y, 0.f);
                __half hx = __float2half_rn(ox_), hy = __float2half_rn(oy_);
                __half lx = __float2half_rn(ox_ - __half2float(hx));
                __half ly = __float2half_rn(oy_ - __half2float(hy));
                __half2 oh = __halves2half2(hx, hy);
                __half2 ol = __halves2half2(lx, ly);
                size_t idx = (size_t)mo * 256 + col;
                *(__half2*)&outh[idx] = oh;
                *(__half2*)&outl[idx] = ol;
            }
        }
    }
}

// ---------------------------------------------------------------------------
// conv2 as 4-term fp16-split mma, BK=16, ldmatrix. A PRE-SPLIT from conv1.
// ---------------------------------------------------------------------------
template<int Cin, int Cout, int IH, int IW, int OH, int OW>
__global__ __launch_bounds__(256) void mma_conv2(
    const __half* __restrict__ inh, const __half* __restrict__ inl,
    const __half* __restrict__ whi, const __half* __restrict__ wlo,
    const float* __restrict__ bias, float* __restrict__ out)
{
    constexpr int BM = 128, BN = 128, BK = 16, LDAH = 24;
    constexpr int MI = 4, NI = 4;
    constexpr int NCI = Cin / BK;
    constexpr int NS = 16 * NCI;
    constexpr int Ktot = 16 * Cin;
    constexpr int TP = BM * LDAH;
    constexpr int STAGE = 4 * TP;

    extern __shared__ __half smh[];
    const uint32_t sbase = smem_u32(smh);

    const int tid = threadIdx.x;
    const int wid = tid >> 5, lid = tid & 31;
    const int g = lid >> 2, t = lid & 3;
    const int wm0 = (wid >> 2) * 64;
    const int wn0 = (wid & 3) * 32;
    const int nblk = blockIdx.x * BN;
    const int mblk = blockIdx.y * BM;

    uint32_t offA[MI], offB[NI];
    #pragma unroll
    for (int mi = 0; mi < MI; mi++) {
        int rowA = wm0 + mi * 16 + ((lid >> 3) & 1) * 8 + (lid & 7);
        int koffA = (lid >> 4) * 8;
        offA[mi] = (uint32_t)(rowA * LDAH + koffA) * 2;
    }
    #pragma unroll
    for (int ni = 0; ni < NI; ni++) {
        int rowB = wn0 + ni * 8 + (lid & 7);
        int koffB = ((lid >> 3) & 1) * 8;
        offB[ni] = (uint32_t)(rowB * LDAH + koffB) * 2;
    }

    uint4 aFh, aFl, bFh, bFl;

    auto loadRegs = [&](int s) {
        const int tap = s / NCI;
        const int ci0 = (s - tap * NCI) * BK;
        const int kh = tap >> 2, kw = tap & 3;
        const int row = tid >> 1, h8 = tid & 1;
        int m = mblk + row;
        int ox = m % OW; int tmp = m / OW; int oy = tmp % OH; int b = tmp / OH;
        int iy = 2 * oy - 1 + kh, ix = 2 * ox - 1 + kw;
        bool ok = (iy >= 0 && iy < IH && ix >= 0 && ix < IW);
        size_t aidx = (size_t)((b * IH + iy) * IW + ix) * Cin + ci0 + h8 * 8;
        uint4 z = make_uint4(0u, 0u, 0u, 0u);
        aFh = ok ? *(const uint4*)&inh[aidx] : z;
        aFl = ok ? *(const uint4*)&inl[aidx] : z;
        const int kbase = (kh * 4 + kw) * Cin + ci0 + h8 * 8;
        bFh = *(const uint4*)&whi[(size_t)(nblk + row) * Ktot + kbase];
        bFl = *(const uint4*)&wlo[(size_t)(nblk + row) * Ktot + kbase];
    };
    auto storeSmem = [&](int buf) {
        const int row = tid >> 1, h8 = tid & 1;
        __half* Ahi = smh + buf * STAGE;
        __half* Alo = Ahi + TP;
        __half* Bhi = Alo + TP;
        __half* Blo = Bhi + TP;
        *(uint4*)&Ahi[row * LDAH + h8 * 8] = aFh;
        *(uint4*)&Alo[row * LDAH + h8 * 8] = aFl;
        *(uint4*)&Bhi[row * LDAH + h8 * 8] = bFh;
        *(uint4*)&Blo[row * LDAH + h8 * 8] = bFl;
    };

    float acc[MI][NI][4];
    #pragma unroll
    for (int mi = 0; mi < MI; mi++)
        #pragma unroll
        for (int ni = 0; ni < NI; ni++)
            #pragma unroll
            for (int c = 0; c < 4; c++) acc[mi][ni][c] = 0.f;

    loadRegs(0);
    storeSmem(0);
    __syncthreads();
    int buf = 0;
    #pragma unroll 1
    for (int s = 0; s < NS; s++) {
        if (s + 1 < NS) loadRegs(s + 1);
        uint32_t AhiB = sbase + (buf * STAGE) * 2;
        uint32_t AloB = AhiB + TP * 2;
        uint32_t BhiB = AloB + TP * 2;
        uint32_t BloB = BhiB + TP * 2;
        uint32_t ah[MI][4], al[MI][4], bh[NI][2], bl[NI][2];
        #pragma unroll
        for (int mi = 0; mi < MI; mi++) {
            ldsm_x4(ah[mi], AhiB + offA[mi]);
            ldsm_x4(al[mi], AloB + offA[mi]);
        }
        #pragma unroll
        for (int ni = 0; ni < NI; ni++) {
            ldsm_x2(bh[ni], BhiB + offB[ni]);
            ldsm_x2(bl[ni], BloB + offB[ni]);
        }
        #pragma unroll
        for (int mi = 0; mi < MI; mi++)
            #pragma unroll
            for (int ni = 0; ni < NI; ni++) {
                mma_f16(acc[mi][ni], ah[mi], bh[ni]);
                mma_f16(acc[mi][ni], ah[mi], bl[ni]);
                mma_f16(acc[mi][ni], al[mi], bh[ni]);
                mma_f16(acc[mi][ni], al[mi], bl[ni]);
            }
        if (s + 1 < NS) {
            storeSmem(buf ^ 1);
            __syncthreads();
            buf ^= 1;
        }
    }

    #pragma unroll
    for (int mi = 0; mi < MI; mi++) {
        #pragma unroll
        for (int half = 0; half < 2; half++) {
            int m = mblk + wm0 + mi * 16 + g + half * 8;
            #pragma unroll
            for (int ni = 0; ni < NI; ni++) {
                int col = nblk + wn0 + ni * 8 + 2 * t;
                float2 bv = *(const float2*)&bias[col];
                float2 o;
                o.x = fmaxf(acc[mi][ni][half * 2 + 0] + bv.x, 0.f);
                o.y = fmaxf(acc[mi][ni][half * 2 + 1] + bv.y, 0.f);
                *(float2*)&out[(size_t)m * Cout + col] = o;
            }
        }
    }
}

// ---------------------------------------------------------------------------
// conv3: exact fp32 SIMT implicit GEMM, split-K x8 (argmin-critical; exact).
// ---------------------------------------------------------------------------
template<int BM, int BN, int BK, int TM, int TN,
         int Cin, int Cout, int IH, int IW, int OH, int OW, int KSPLIT>
__global__ __launch_bounds__(256) void conv_s2_gemm(
    const float* __restrict__ in, const float* __restrict__ w,
    const float* __restrict__ bias, float* __restrict__ out)
{
    static_assert((BM / TM) * (BN / TN) == 256, "thread count");
    constexpr int NCI   = Cin / BK;
    constexpr int NS    = 16 * NCI;
    constexpr int NSC   = NS / KSPLIT;
    constexpr int MTOT  = 32 * OH * OW;
    constexpr int ALOOP = (BM * BK / 4) / 256;
    constexpr int BLOOP = (BK * BN / 4) / 256;
    static_assert(ALOOP >= 1 && BLOOP >= 1, "load split");
    static_assert(NSC >= 2, "pipeline");

    __shared__ __align__(16) float As[2][BK][BM + 4];
    __shared__ __align__(16) float Bs[2][BK][BN + 4];

    const int tid  = threadIdx.x;
    const int mblk = blockIdx.y * BM;
    const int kc   = (KSPLIT > 1) ? (int)blockIdx.x : 0;
    const int nblk = (KSPLIT > 1) ? 0 : blockIdx.x * BN;

    float4 areg[ALOOP], breg[BLOOP];

    auto loadRegs = [&](int s) {
        int t16 = s / NCI;
        int ci0 = (s % NCI) * BK;
        int kh = t16 >> 2, kw = t16 & 3;
        #pragma unroll
        for (int i = 0; i < ALOOP; i++) {
            int idx = tid + i * 256;
            int row = idx / (BK / 4);
            int c4  = idx % (BK / 4);
            int m   = mblk + row;
            int ox  = m % OW;
            int tmp = m / OW;
            int oy  = tmp % OH;
            int b   = tmp / OH;
            int iy  = 2 * oy - 1 + kh;
            int ix  = 2 * ox - 1 + kw;
            if (iy >= 0 && iy < IH && ix >= 0 && ix < IW)
                areg[i] = *(const float4*)&in[((b * IH + iy) * IW + ix) * Cin + ci0 + c4 * 4];
            else
                areg[i] = make_float4(0.f, 0.f, 0.f, 0.f);
        }
        #pragma unroll
        for (int i = 0; i < BLOOP; i++) {
            int idx  = tid + i * 256;
            int krow = idx / (BN / 4);
            int c4   = idx % (BN / 4);
            breg[i] = *(const float4*)&w[(t16 * Cin + ci0 + krow) * Cout + nblk + c4 * 4];
        }
    };
    auto storeSmem = [&](int buf) {
        #pragma unroll
        for (int i = 0; i < ALOOP; i++) {
            int idx = tid + i * 256;
            int row = idx / (BK / 4);
            int c4  = idx % (BK / 4);
            As[buf][c4 * 4 + 0][row] = areg[i].x;
            As[buf][c4 * 4 + 1][row] = areg[i].y;
            As[buf][c4 * 4 + 2][row] = areg[i].z;
            As[buf][c4 * 4 + 3][row] = areg[i].w;
        }
        #pragma unroll
        for (int i = 0; i < BLOOP; i++) {
            int idx  = tid + i * 256;
            int krow = idx / (BN / 4);
            int c4   = idx % (BN / 4);
            *(float4*)&Bs[buf][krow][c4 * 4] = breg[i];
        }
    };

    const int ty = tid / (BN / TN);
    const int tx = tid % (BN / TN);
    float acc[TM][TN];
    #pragma unroll
    for (int i = 0; i < TM; i++)
        #pragma unroll
        for (int j = 0; j < TN; j++) acc[i][j] = 0.f;

    const int s0 = kc * NSC;
    loadRegs(s0);
    storeSmem(0);
    __syncthreads();
    int buf = 0;
    for (int s = s0; s < s0 + NSC; s++) {
        if (s + 1 < s0 + NSC) loadRegs(s + 1);
        #pragma unroll
        for (int kk = 0; kk < BK; kk++) {
            float a[TM], bb[TN];
            #pragma unroll
            for (int i = 0; i < TM; i += 4)
                *(float4*)&a[i] = *(const float4*)&As[buf][kk][ty * TM + i];
            #pragma unroll
            for (int j = 0; j < TN; j += 4)
                *(float4*)&bb[j] = *(const float4*)&Bs[buf][kk][tx * TN + j];
            #pragma unroll
            for (int i = 0; i < TM; i++)
                #pragma unroll
                for (int j = 0; j < TN; j++)
                    acc[i][j] = fmaf(a[i], bb[j], acc[i][j]);
        }
        if (s + 1 < s0 + NSC) {
            storeSmem(buf ^ 1);
            __syncthreads();
            buf ^= 1;
        }
    }
    #pragma unroll
    for (int i = 0; i < TM; i++) {
        int m = mblk + ty * TM + i;
        #pragma unroll
        for (int j = 0; j < TN; j++) {
            int n = nblk + tx * TN + j;
            if (KSPLIT > 1) {
                out[(size_t)kc * MTOT * Cout + (size_t)m * Cout + n] = acc[i][j];
            } else {
                float v = acc[i][j] + bias[n];
                out[(size_t)m * Cout + n] = fmaxf(v, 0.f);
            }
        }
    }
}

__global__ __launch_bounds__(256) void reduce_z_kernel(const float* __restrict__ bias) {
    int i = blockIdx.x * 256 + threadIdx.x;
    float s = 0.f;
    #pragma unroll
    for (int kc = 0; kc < 8; kc++)
        s += g_zpart[kc * 8192 * 64 + i];
    g_z[i] = fmaxf(s + bias[i & 63], 0.f);
}

// ---------------------------------------------------------------------------
// Decoder transposed conv: fp16 mma with ldmatrix. IN_HALF: A pre-converted
// fp16 (bit-identical to on-the-fly cvt). OUT_HALF: epilogue stores fp16.
// ---------------------------------------------------------------------------
template<int BM, int BN, int WARPS_M, int WARPS_N, int Cin, int Cout,
         int ISP, int OSP, bool IN_HALF, bool OUT_HALF,
         typename TIn, typename TOut>
__global__ __launch_bounds__(256) void mma_deconv(
    const TIn* __restrict__ in, const __half* __restrict__ wth,
    const float* __restrict__ bias, TOut* __restrict__ out)
{
    constexpr int BK = 16, LDAH = 24;
    constexpr int WM = BM / WARPS_M, WN = BN / WARPS_N;
    constexpr int MI = WM / 16, NI = WN / 8;
    constexpr int NCI = Cin / BK;
    constexpr int NS = 4 * NCI;
    constexpr int Ktot = 16 * Cin;
    constexpr int ALOOP = (BM * 4) / 256;
    constexpr int APITCH = BM * LDAH;
    constexpr int BPITCH = BN * LDAH;
    static_assert(WARPS_M * WARPS_N == 8, "8 warps");
    static_assert(ALOOP >= 1, "load split");
    static_assert(BN * 2 == 256, "B load mapping");

    extern __shared__ __half smh[];
    __half* Abase = smh;
    __half* Bbase = smh + 2 * APITCH;
    const uint32_t sbase = smem_u32(smh);

    const int tid = threadIdx.x;
    const int wid = tid >> 5, lid = tid & 31;
    const int g = lid >> 2, t = lid & 3;
    const int wm0 = (wid / WARPS_N) * WM;
    const int wn0 = (wid % WARPS_N) * WN;
    const int nblk = blockIdx.x * BN;
    const int mblk = blockIdx.y * BM;
    const int par  = blockIdx.z;
    const int py = par >> 1, px = par & 1;

    uint32_t offA[MI], offB[NI];
    #pragma unroll
    for (int mi = 0; mi < MI; mi++) {
        int rowA = wm0 + mi * 16 + ((lid >> 3) & 1) * 8 + (lid & 7);
        int koffA = (lid >> 4) * 8;
        offA[mi] = (uint32_t)(rowA * LDAH + koffA) * 2;
    }
    #pragma unroll
    for (int ni = 0; ni < NI; ni++) {
        int rowB = wn0 + ni * 8 + (lid & 7);
        int koffB = ((lid >> 3) & 1) * 8;
        offB[ni] = (uint32_t)(rowB * LDAH + koffB) * 2;
    }

    float4 aF[ALOOP];
    uint2  aH[ALOOP];
    uint4  bF;

    auto loadRegs = [&](int s) {
        const int tap = s / NCI;
        const int ci0 = (s - tap * NCI) * BK;
        int tyk = tap >> 1, txk = tap & 1;
        int kh = (py ? 2 : 3) - 2 * tyk;
        int kw = (px ? 2 : 3) - 2 * txk;
        #pragma unroll
        for (int i = 0; i < ALOOP; i++) {
            int slot = tid + i * 256;
            int row = slot >> 2, c4 = slot & 3;
            int m = mblk + row;
            int mx = m % ISP; int t2 = m / ISP; int my = t2 % ISP; int b = t2 / ISP;
            int iy = my + tyk - 1 + py;
            int ix = mx + txk - 1 + px;
            bool ok = (iy >= 0 && iy < ISP && ix >= 0 && ix < ISP);
            size_t aidx = (size_t)((b * ISP + iy) * ISP + ix) * Cin + ci0 + c4 * 4;
            if (IN_HALF) {
                aH[i] = ok ? *(const uint2*)&in[aidx] : make_uint2(0u, 0u);
            } else {
                aF[i] = ok ? *(const float4*)&((const float*)in)[aidx]
                           : make_float4(0.f, 0.f, 0.f, 0.f);
            }
        }
        const int kbase = (kh * 4 + kw) * Cin + ci0;
        {
            int row = tid >> 1, h8 = tid & 1;
            bF = *(const uint4*)&wth[(size_t)(nblk + row) * Ktot + kbase + h8 * 8];
        }
    };
    auto storeSmem = [&](int buf) {
        #pragma unroll
        for (int i = 0; i < ALOOP; i++) {
            int slot = tid + i * 256;
            int row = slot >> 2, c4 = slot & 3;
            uint2 st;
            if (IN_HALF) {
                st = aH[i];
            } else {
                float4 v = aF[i];
                __half2 p0 = __floats2half2_rn(v.x, v.y);
                __half2 p1 = __floats2half2_rn(v.z, v.w);
                st.x = *(uint32_t*)&p0;
                st.y = *(uint32_t*)&p1;
            }
            *(uint2*)&Abase[buf * APITCH + row * LDAH + c4 * 4] = st;
        }
        {
            int row = tid >> 1, h8 = tid & 1;
            *(uint4*)&Bbase[buf * BPITCH + row * LDAH + h8 * 8] = bF;
        }
    };

    float acc[MI][NI][4];
    #pragma unroll
    for (int mi = 0; mi < MI; mi++)
        #pragma unroll
        for (int ni = 0; ni < NI; ni++)
            #pragma unroll
            for (int c = 0; c < 4; c++) acc[mi][ni][c] = 0.f;

    loadRegs(0);
    storeSmem(0);
    __syncthreads();
    int buf = 0;
    #pragma unroll 1
    for (int s = 0; s < NS; s++) {
        if (s + 1 < NS) loadRegs(s + 1);
        uint32_t AB = sbase + (buf * APITCH) * 2;
        uint32_t BB = sbase + (2 * APITCH + buf * BPITCH) * 2;
        uint32_t au[MI][4], bu[NI][2];
        #pragma unroll
        for (int mi = 0; mi < MI; mi++)
            ldsm_x4(au[mi], AB + offA[mi]);
        #pragma unroll
        for (int ni = 0; ni < NI; ni++)
            ldsm_x2(bu[ni], BB + offB[ni]);
        #pragma unroll
        for (int mi = 0; mi < MI; mi++)
            #pragma unroll
            for (int ni = 0; ni < NI; ni++)
                mma_f16(acc[mi][ni], au[mi], bu[ni]);
        if (s + 1 < NS) {
            storeSmem(buf ^ 1);
            __syncthreads();
            buf ^= 1;
        }
    }

    #pragma unroll
    for (int mi = 0; mi < MI; mi++) {
        #pragma unroll
        for (int half = 0; half < 2; half++) {
            int m = mblk + wm0 + mi * 16 + g + half * 8;
            int mx = m % ISP; int t2 = m / ISP; int my = t2 % ISP; int b = t2 / ISP;
            size_t obase = ((size_t)(b * OSP + 2 * my + py) * OSP + 2 * mx + px) * Cout;
            #pragma unroll
            for (int ni = 0; ni < NI; ni++) {
                int col = nblk + wn0 + ni * 8 + 2 * t;
                float2 bv = *(const float2*)&bias[col];
                float ox_ = fmaxf(acc[mi][ni][half * 2 + 0] + bv.x, 0.f);
                float oy_ = fmaxf(acc[mi][ni][half * 2 + 1] + bv.y, 0.f);
                if (OUT_HALF) {
                    __half2 oh = __floats2half2_rn(ox_, oy_);
                    *(__half2*)&((__half*)out)[obase + col] = oh;
                } else {
                    float2 o; o.x = ox_; o.y = oy_;
                    *(float2*)&((float*)out)[obase + col] = o;
                }
            }
        }
    }
}

// ---------------------------------------------------------------------------
// VQ: 8 lane-groups per pixel over 64 codes each; shfl argmin reduce. Exact.
// ---------------------------------------------------------------------------
__global__ __launch_bounds__(256) void vq_kernel(const float* __restrict__ cb) {
    const int lid = threadIdx.x & 31, wrp = threadIdx.x >> 5;
    const int pixw = lid & 3, grp = lid >> 2;
    const int p = blockIdx.x * 32 + wrp * 4 + pixw;

    float z[64];
    const float4* zp = (const float4*)&g_z[p * 64];
    #pragma unroll
    for (int j4 = 0; j4 < 16; j4++) {
        float4 v = zp[j4];
        z[j4 * 4 + 0] = v.x; z[j4 * 4 + 1] = v.y;
        z[j4 * 4 + 2] = v.z; z[j4 * 4 + 3] = v.w;
    }
    float best = 3.4e38f;
    int bi = 0;
    for (int c = grp * 64; c < grp * 64 + 64; c++) {
        const float4* cp = (const float4*)&cb[c * 64];
        float dot = 0.f;
        #pragma unroll
        for (int j4 = 0; j4 < 16; j4++) {
            float4 v = __ldg(&cp[j4]);
            dot = fmaf(z[j4 * 4 + 0], v.x, dot);
            dot = fmaf(z[j4 * 4 + 1], v.y, dot);
            dot = fmaf(z[j4 * 4 + 2], v.z, dot);
            dot = fmaf(z[j4 * 4 + 3], v.w, dot);
        }
        float d = g_cnorm[c] - 2.f * dot;
        if (d < best) { best = d; bi = c; }
    }
    #pragma unroll
    for (int off = 4; off <= 16; off <<= 1) {
        float ob = __shfl_xor_sync(0xFFFFFFFFu, best, off);
        int  obi = __shfl_xor_sync(0xFFFFFFFFu, bi,   off);
        if (ob < best || (ob == best && obi < bi)) { best = ob; bi = obi; }
    }

    float ls = 0.f;
    if (grp == 0) {
        float4* qp = (float4*)&g_q[p * 64];
        const float4* cbest = (const float4*)&cb[bi * 64];
        #pragma unroll
        for (int j4 = 0; j4 < 16; j4++) {
            float4 v = cbest[j4];
            qp[j4] = v;
            float d0 = z[j4 * 4 + 0] - v.x;
            float d1 = z[j4 * 4 + 1] - v.y;
            float d2 = z[j4 * 4 + 2] - v.z;
            float d3 = z[j4 * 4 + 3] - v.w;
            ls = fmaf(d0, d0, ls); ls = fmaf(d1, d1, ls);
            ls = fmaf(d2, d2, ls); ls = fmaf(d3, d3, ls);
        }
        g_used[bi] = 1;
    }

    __shared__ float red[256];
    red[threadIdx.x] = ls;
    __syncthreads();
    for (int s2 = 128; s2 > 0; s2 >>= 1) {
        if (threadIdx.x < s2) red[threadIdx.x] += red[threadIdx.x + s2];
        __syncthreads();
    }
    if (threadIdx.x == 0) g_partial[blockIdx.x] = red[0];
}

// ---------------------------------------------------------------------------
// deconv3: 256->3, sigmoid, NHWC in -> NCHW out (exact). 2 rows per block.
// ---------------------------------------------------------------------------
__global__ __launch_bounds__(256) void deconv3_kernel(
    const float* __restrict__ in, const float* __restrict__ w,
    const float* __restrict__ bias, float* __restrict__ out)
{
    __shared__ float ws[16 * 3 * 256];   // [tap][c][ci]
    for (int i = threadIdx.x; i < 16 * 3 * 256; i += 256) {
        int tap = i / 768;
        int rem = i - tap * 768;
        int c = rem >> 8;
        int ci = rem & 255;
        ws[i] = w[(tap * 256 + ci) * 3 + c];
    }
    __syncthreads();

    int b  = blockIdx.x >> 6;
    int oy = ((blockIdx.x & 63) << 1) | (threadIdx.x >> 7);
    int ox = threadIdx.x & 127;
    int py = oy & 1, px = ox & 1;
    int my = oy >> 1, mx = ox >> 1;

    float acc0 = bias[0], acc1 = bias[1], acc2 = bias[2];
    #pragma unroll
    for (int t = 0; t < 4; t++) {
        int tyk = t >> 1, txk = t & 1;
        int iy = my + tyk - 1 + py;
        int ix = mx + txk - 1 + px;
        if (iy < 0 || iy >= 64 || ix < 0 || ix >= 64) continue;
        int kh = (py ? 2 : 3) - 2 * tyk;
        int kw = (px ? 2 : 3) - 2 * txk;
        const float* ip  = &in[((b * 64 + iy) * 64 + ix) * 256];
        const float* wp0 = &ws[((kh * 4 + kw) * 3 + 0) * 256];
        const float* wp1 = &ws[((kh * 4 + kw) * 3 + 1) * 256];
        const float* wp2 = &ws[((kh * 4 + kw) * 3 + 2) * 256];
        #pragma unroll 8
        for (int ci = 0; ci < 256; ci += 4) {
            float4 v  = *(const float4*)&ip[ci];
            float4 w0 = *(const float4*)&wp0[ci];
            float4 w1 = *(const float4*)&wp1[ci];
            float4 w2 = *(const float4*)&wp2[ci];
            acc0 = fmaf(v.x, w0.x, acc0);
            acc1 = fmaf(v.x, w1.x, acc1);
            acc2 = fmaf(v.x, w2.x, acc2);
            acc0 = fmaf(v.y, w0.y, acc0);
            acc1 = fmaf(v.y, w1.y, acc1);
            acc2 = fmaf(v.y, w2.y, acc2);
            acc0 = fmaf(v.z, w0.z, acc0);
            acc1 = fmaf(v.z, w1.z, acc1);
            acc2 = fmaf(v.z, w2.z, acc2);
            acc0 = fmaf(v.w, w0.w, acc0);
            acc1 = fmaf(v.w, w1.w, acc1);
            acc2 = fmaf(v.w, w2.w, acc2);
        }
    }
    out[((b * 3 + 0) * 128 + oy) * 128 + ox] = 1.f / (1.f + expf(-acc0));
    out[((b * 3 + 1) * 128 + oy) * 128 + ox] = 1.f / (1.f + expf(-acc1));
    out[((b * 3 + 2) * 128 + oy) * 128 + ox] = 1.f / (1.f + expf(-acc2));
}

__global__ void finalize_kernel(float* __restrict__ out, int out_size) {
    __shared__ int total;
    int t = threadIdx.x;
    if (t == 0) total = 0;
    __syncthreads();
    if (t < 512 && g_used[t]) atomicAdd(&total, 1);
    __syncthreads();
    if (t == 0) {
        float sum = 0.f;
        for (int i = 0; i < 256; i++) sum += g_partial[i];
        float mean = sum / (float)(8192 * 64);
        out[out_size - 3] = mean;
        out[out_size - 2] = mean;
        out[out_size - 1] = (float)total;
    }
}

// ---------------------------------------------------------------------------
extern "C" void kernel_launch(void* const* d_in, const int* in_sizes, int n_in,
                              void* d_out, int out_size)
{
    const float* x   = (const float*)d_in[0];
    const float* ew1 = (const float*)d_in[1];
    const float* eb1 = (const float*)d_in[2];
    const float* ew2 = (const float*)d_in[3];
    const float* eb2 = (const float*)d_in[4];
    const float* ew3 = (const float*)d_in[5];
    const float* eb3 = (const float*)d_in[6];
    const float* cb  = (const float*)d_in[7];
    const float* dw1 = (const float*)d_in[8];
    const float* db1 = (const float*)d_in[9];
    const float* dw2 = (const float*)d_in[10];
    const float* db2 = (const float*)d_in[11];
    const float* dw3 = (const float*)d_in[12];
    const float* db3 = (const float*)d_in[13];
    float* out = (float*)d_out;

    float *h2, *zpart, *q, *d2;
    __half *h1h, *h1l, *d1h, *we1h, *we1l, *we2h, *we2l, *wd1h, *wd2h;
    cudaGetSymbolAddress((void**)&h1h, g_h1h);
    cudaGetSymbolAddress((void**)&h1l, g_h1l);
    cudaGetSymbolAddress((void**)&h2, g_h2);
    cudaGetSymbolAddress((void**)&zpart, g_zpart);
    cudaGetSymbolAddress((void**)&q,  g_q);
    cudaGetSymbolAddress((void**)&d1h, g_d1h);
    cudaGetSymbolAddress((void**)&d2, g_d2);
    cudaGetSymbolAddress((void**)&we1h, g_we1h);
    cudaGetSymbolAddress((void**)&we1l, g_we1l);
    cudaGetSymbolAddress((void**)&we2h, g_we2h);
    cudaGetSymbolAddress((void**)&we2l, g_we2l);
    cudaGetSymbolAddress((void**)&wd1h, g_wd1h);
    cudaGetSymbolAddress((void**)&wd2h, g_wd2h);

    const int SM_DEC = 2 * (128 * 24 + 128 * 24) * 2;   // 24576 B
    const int SM_MMA = 2 * 4 * 128 * 24 * 2;            // 49152 B
    cudaFuncSetAttribute(mma_conv1,
                         cudaFuncAttributeMaxDynamicSharedMemorySize, SM_MMA);
    cudaFuncSetAttribute(mma_conv2<256, 512, 64, 64, 32, 32>,
                         cudaFuncAttributeMaxDynamicSharedMemorySize, SM_MMA);

    cnorm_kernel<<<2, 256>>>(cb);

    // weight prep
    wtrans_c1<<<1, 256>>>(ew1, we1h, we1l);
    wtrans_half2<<<dim3(4096 / 32, 512 / 32), 256>>>(ew2, we2h, we2l, 4096, 512);
    wtrans_half<<<dim3(1024 / 32, 512 / 32), 256>>>(dw1, wd1h, 1024, 512);
    wtrans_half<<<dim3(8192 / 32, 256 / 32), 256>>>(dw2, wd2h, 8192, 256);

    // encoder
    mma_conv1<<<dim3(2, 1024), 256, SM_MMA>>>(x, we1h, we1l, eb1, h1h, h1l);
    mma_conv2<256, 512, 64, 64, 32, 32>
        <<<dim3(4, 256), 256, SM_MMA>>>(h1h, h1l, we2h, we2l, eb2, h2);
    conv_s2_gemm<128, 64, 16, 8, 4, 512, 64, 32, 32, 16, 16, 8>
        <<<dim3(8, 64), 256>>>(h2, ew3, eb3, zpart);
    reduce_z_kernel<<<2048, 256>>>(eb3);

    // vector quantize (exact)
    vq_kernel<<<256, 256>>>(cb);

    // decoder (fp16 tensor, ldmatrix; d1 stored as fp16)
    mma_deconv<128, 128, 2, 4, 64, 512, 16, 32, false, true, float, __half>
        <<<dim3(4, 64, 4), 256, SM_DEC>>>(q, wd1h, db1, d1h);
    mma_deconv<128, 128, 2, 4, 512, 256, 32, 64, true, false, __half, float>
        <<<dim3(2, 256, 4), 256, SM_DEC>>>(d1h, wd2h, db2, d2);
    deconv3_kernel<<<32 * 64, 256>>>(d2, dw3, db3, out);

    finalize_kernel<<<1, 512>>>(out, out_size);
}